// round 1
// baseline (speedup 1.0000x reference)
#include <cuda_runtime.h>
#include <cuda_bf16.h>
#include <math.h>

// Problem constants
#define Bz 4
#define Nn 2048
#define Dd 512
#define Hh 8
#define Cc 64
#define HC 512   // H*C

// Scratch (device globals — no allocation allowed in kernel_launch)
__device__ float g_X[(size_t)Bz * Nn * HC];      // projected features [B,N,HC]
__device__ float g_asrc[(size_t)Bz * Nn * Hh];   // [B,N,H]
__device__ float g_adst[(size_t)Bz * Nn * Hh];   // [B,N,H]

// ---------------------------------------------------------------------------
// Fast exp: FFMA-only (avoids MUFU bottleneck: 134M exps would cost ~950us on
// the MUFU pipe). Magic-number round + degree-5 poly, rel err ~2.4e-6.
// Valid for |x| < ~80, which holds (logits bounded ~ +-10).
// ---------------------------------------------------------------------------
__device__ __forceinline__ float fexp(float x) {
    const float LOG2E = 1.4426950408889634f;
    float t = x * LOG2E;
    float z = t + 12582912.0f;                    // 1.5 * 2^23: round-to-nearest
    int   n = __float_as_int(z) - 0x4B400000;     // integer part
    float r = z - 12582912.0f;
    float f = t - r;                              // frac in [-0.5, 0.5]
    float u = f * 0.69314718056f;                 // back to natural log domain
    float p = 8.3333333e-3f;                      // 1/120
    p = p * u + 4.1666667e-2f;                    // 1/24
    p = p * u + 1.6666667e-1f;                    // 1/6
    p = p * u + 0.5f;
    p = p * u + 1.0f;
    p = p * u + 1.0f;
    float s = __int_as_float((n + 127) << 23);    // 2^n
    return p * s;
}

// ---------------------------------------------------------------------------
// Kernel 1: projection GEMM  X[8192,512] = F[8192,512] @ W[512,512]  (fp32)
// Block tile 128x64, k-tile 8, 128 threads, 8x8 per-thread register tile.
// ---------------------------------------------------------------------------
__global__ __launch_bounds__(128) void gemm_proj(
    const float* __restrict__ A, const float* __restrict__ Wm)
{
    __shared__ float As[8][128];
    __shared__ float Bs[8][64];

    const int m0 = blockIdx.x * 128;
    const int n0 = blockIdx.y * 64;
    const int t  = threadIdx.x;
    const int ty = t >> 3;   // 0..15 (row group)
    const int tx = t & 7;    // 0..7  (col group)

    float acc[8][8];
    #pragma unroll
    for (int i = 0; i < 8; i++)
        #pragma unroll
        for (int j = 0; j < 8; j++) acc[i][j] = 0.f;

    for (int k0 = 0; k0 < Dd; k0 += 8) {
        // Load A tile: 128 rows x 8 k — thread t loads one row's 8 floats
        const float* ap = A + (size_t)(m0 + t) * Dd + k0;
        float4 a0 = *(const float4*)ap;
        float4 a1 = *(const float4*)(ap + 4);
        As[0][t] = a0.x; As[1][t] = a0.y; As[2][t] = a0.z; As[3][t] = a0.w;
        As[4][t] = a1.x; As[5][t] = a1.y; As[6][t] = a1.z; As[7][t] = a1.w;
        // Load B tile: 8 rows x 64 cols — thread loads one float4
        {
            int br = t >> 4;          // 0..7
            int bc = (t & 15) << 2;   // 0..60
            *(float4*)&Bs[br][bc] =
                *(const float4*)(Wm + (size_t)(k0 + br) * HC + n0 + bc);
        }
        __syncthreads();

        #pragma unroll
        for (int k = 0; k < 8; k++) {
            float af[8], bf[8];
            *(float4*)(af)     = *(const float4*)&As[k][ty * 8];
            *(float4*)(af + 4) = *(const float4*)&As[k][ty * 8 + 4];
            *(float4*)(bf)     = *(const float4*)&Bs[k][tx * 8];
            *(float4*)(bf + 4) = *(const float4*)&Bs[k][tx * 8 + 4];
            #pragma unroll
            for (int i = 0; i < 8; i++)
                #pragma unroll
                for (int j = 0; j < 8; j++)
                    acc[i][j] += af[i] * bf[j];
        }
        __syncthreads();
    }

    #pragma unroll
    for (int i = 0; i < 8; i++) {
        float* op = g_X + (size_t)(m0 + ty * 8 + i) * HC + n0 + tx * 8;
        *(float4*)op       = make_float4(acc[i][0], acc[i][1], acc[i][2], acc[i][3]);
        *(float4*)(op + 4) = make_float4(acc[i][4], acc[i][5], acc[i][6], acc[i][7]);
    }
}

// ---------------------------------------------------------------------------
// Kernel 2: per-node attention scores a_src/a_dst [B,N,H]
// One thread per (b,n,h); 64-length dots, fully unrolled float4.
// ---------------------------------------------------------------------------
__global__ __launch_bounds__(256) void att_scores(
    const float* __restrict__ att_src, const float* __restrict__ att_dst)
{
    int idx = blockIdx.x * blockDim.x + threadIdx.x;
    if (idx >= Bz * Nn * Hh) return;
    int h  = idx & 7;
    int bn = idx >> 3;
    const float* xp = g_X + (size_t)bn * HC + h * Cc;
    const float* ws = att_src + h * Cc;
    const float* wd = att_dst + h * Cc;
    float s = 0.f, d = 0.f;
    #pragma unroll
    for (int c = 0; c < Cc; c += 4) {
        float4 xv = *(const float4*)(xp + c);
        float4 sv = *(const float4*)(ws + c);
        float4 dv = *(const float4*)(wd + c);
        s += xv.x * sv.x + xv.y * sv.y + xv.z * sv.z + xv.w * sv.w;
        d += xv.x * dv.x + xv.y * dv.y + xv.z * dv.z + xv.w * dv.w;
    }
    g_asrc[idx] = s;
    g_adst[idx] = d;
}

// ---------------------------------------------------------------------------
// Kernel 3: fused masked-softmax aggregation + ELU epilogue.
// Block handles (b, 64-target tile, 2 heads). Streams sources i in tiles of 16.
// No online-max needed (logits bounded): out = (sum e*x) / (sum e).
// GEMM phase: 8j x 8c register tiles -> FMA-pipe bound by design.
// ---------------------------------------------------------------------------
#define TJ 64
#define TI 16

__global__ __launch_bounds__(128, 4) void gat_agg(
    const int* __restrict__ adj, const float* __restrict__ bias,
    float* __restrict__ out)
{
    __shared__ float es[TI][2][68];   // [i_local][head_local][j] (+pad: conflict-free frag reads)
    __shared__ float xs[TI][128];     // [i_local][2 heads * 64 c]
    __shared__ float adsts[2][TJ];
    __shared__ float ls[2][TJ];

    const int b  = blockIdx.z;
    const int h0 = blockIdx.y * 2;
    const int j0 = blockIdx.x * TJ;
    const int t  = threadIdx.x;

    // GEMM-phase identity: 8 j-groups x 16 c-groups, 8x8 tile each
    const int jg   = t >> 4;       // 0..7
    const int cg   = t & 15;       // 0..15 (spans 128 hc columns)
    const int hloc = cg >> 3;      // which of the 2 heads my c-columns belong to

    // Phase-1 identity: one (j, head) per thread
    const int pj = t & 63;
    const int ph = t >> 6;

    adsts[ph][pj] = g_adst[((size_t)b * Nn + j0 + pj) * Hh + h0 + ph];
    __syncthreads();
    const float my_adst = adsts[ph][pj];
    float lsum = 0.f;

    float acc[8][8];
    #pragma unroll
    for (int i = 0; i < 8; i++)
        #pragma unroll
        for (int j = 0; j < 8; j++) acc[i][j] = 0.f;

    const int* adjcol = adj + (size_t)b * Nn * Nn + j0;

    for (int i0 = 0; i0 < Nn; i0 += TI) {
        // ---- Phase 1: edge weights e = mask ? exp(leaky_relu(a_src+a_dst)) : 0
        #pragma unroll 4
        for (int il = 0; il < TI; il++) {
            int   i   = i0 + il;
            int   av  = adjcol[(size_t)i * Nn + pj];
            float asr = g_asrc[((size_t)b * Nn + i) * Hh + h0 + ph];
            float lg  = asr + my_adst;
            lg = (lg > 0.f) ? lg : 0.2f * lg;
            float e = ((av != 0) || (i == j0 + pj)) ? fexp(lg) : 0.f;
            es[il][ph][pj] = e;
            lsum += e;   // this thread owns (pj, ph) across all i -> exact l
        }
        // ---- Load x tile: 16 rows x 128 hc (coalesced float4)
        {
            const float* xbase = g_X + ((size_t)b * Nn + i0) * HC + h0 * Cc;
            #pragma unroll
            for (int u = 0; u < 4; u++) {
                int lin = u * 128 + t;      // float4 index, 0..511
                int il  = lin >> 5;         // 32 float4 per 128-wide row
                int hc4 = lin & 31;
                *(float4*)&xs[il][hc4 << 2] =
                    *(const float4*)(xbase + (size_t)il * HC + (hc4 << 2));
            }
        }
        __syncthreads();

        // ---- Phase 2: acc[j][c] += e[i][j] * x[i][c]  (64 FMA / 64B LDS per thread)
        #pragma unroll
        for (int il = 0; il < TI; il++) {
            float ef[8], xf[8];
            *(float4*)(ef)     = *(const float4*)&es[il][hloc][(jg << 3)];
            *(float4*)(ef + 4) = *(const float4*)&es[il][hloc][(jg << 3) + 4];
            *(float4*)(xf)     = *(const float4*)&xs[il][(cg << 3)];
            *(float4*)(xf + 4) = *(const float4*)&xs[il][(cg << 3) + 4];
            #pragma unroll
            for (int jj = 0; jj < 8; jj++)
                #pragma unroll
                for (int cc = 0; cc < 8; cc++)
                    acc[jj][cc] += ef[jj] * xf[cc];
        }
        __syncthreads();
    }

    // ---- Publish softmax denominators
    ls[ph][pj] = lsum;
    __syncthreads();

    // ---- Epilogue: normalize, +bias, ELU, store
    #pragma unroll
    for (int jj = 0; jj < 8; jj++) {
        int   j   = j0 + (jg << 3) + jj;
        float inv = 1.0f / ls[hloc][(jg << 3) + jj];
        float ov[8];
        #pragma unroll
        for (int cc = 0; cc < 8; cc++) {
            int   col = h0 * Cc + (cg << 3) + cc;
            float v   = acc[jj][cc] * inv + bias[col];
            ov[cc] = (v > 0.f) ? v : expm1f(v);
        }
        float* op = out + ((size_t)b * Nn + j) * HC + h0 * Cc + (cg << 3);
        *(float4*)op       = make_float4(ov[0], ov[1], ov[2], ov[3]);
        *(float4*)(op + 4) = make_float4(ov[4], ov[5], ov[6], ov[7]);
    }
}

// ---------------------------------------------------------------------------
// Launch
// ---------------------------------------------------------------------------
extern "C" void kernel_launch(void* const* d_in, const int* in_sizes, int n_in,
                              void* d_out, int out_size)
{
    const float* feats   = (const float*)d_in[0];  // [B,N,D]
    const int*   adj     = (const int*)  d_in[1];  // [B,N,N]
    const float* W       = (const float*)d_in[2];  // [D,HC]
    const float* att_src = (const float*)d_in[3];  // [H,C]
    const float* att_dst = (const float*)d_in[4];  // [H,C]
    const float* bias    = (const float*)d_in[5];  // [HC]
    float*       out     = (float*)d_out;          // [B,N,HC]

    (void)in_sizes; (void)n_in; (void)out_size;

    // 1) projection GEMM -> g_X
    gemm_proj<<<dim3((Bz * Nn) / 128, HC / 64), 128>>>(feats, W);
    // 2) attention scores -> g_asrc / g_adst
    att_scores<<<(Bz * Nn * Hh + 255) / 256, 256>>>(att_src, att_dst);
    // 3) fused masked-softmax aggregation + ELU -> out
    gat_agg<<<dim3(Nn / TJ, Hh / 2, Bz), 128>>>(adj, bias, out);
}

// round 2
// speedup vs baseline: 1.0016x; 1.0016x over previous
#include <cuda_runtime.h>
#include <cuda_bf16.h>
#include <math.h>

// Problem constants
#define Bz 4
#define Nn 2048
#define Dd 512
#define Hh 8
#define Cc 64
#define HC 512   // H*C

// Scratch (device globals — no allocation allowed in kernel_launch)
__device__ float g_X[(size_t)Bz * Nn * HC];      // projected features [B,N,HC]
__device__ float g_asrc[(size_t)Bz * Nn * Hh];   // [B,N,H]
__device__ float g_adst[(size_t)Bz * Nn * Hh];   // [B,N,H]

// ---------------------------------------------------------------------------
// Fast exp: FFMA-only (avoids MUFU bottleneck: 134M exps would cost ~950us on
// the MUFU pipe). Magic-number round + degree-5 poly, rel err ~2.4e-6.
// Valid for |x| < ~80, which holds (logits bounded ~ +-10).
// ---------------------------------------------------------------------------
__device__ __forceinline__ float fexp(float x) {
    const float LOG2E = 1.4426950408889634f;
    float t = x * LOG2E;
    float z = t + 12582912.0f;                    // 1.5 * 2^23: round-to-nearest
    int   n = __float_as_int(z) - 0x4B400000;     // integer part
    float r = z - 12582912.0f;
    float f = t - r;                              // frac in [-0.5, 0.5]
    float u = f * 0.69314718056f;                 // back to natural log domain
    float p = 8.3333333e-3f;                      // 1/120
    p = p * u + 4.1666667e-2f;                    // 1/24
    p = p * u + 1.6666667e-1f;                    // 1/6
    p = p * u + 0.5f;
    p = p * u + 1.0f;
    p = p * u + 1.0f;
    float s = __int_as_float((n + 127) << 23);    // 2^n
    return p * s;
}

// ---------------------------------------------------------------------------
// Kernel 1: projection GEMM  X[8192,512] = F[8192,512] @ W[512,512]  (fp32)
// Block tile 128x64, k-tile 8, 128 threads, 8x8 per-thread register tile.
// ---------------------------------------------------------------------------
__global__ __launch_bounds__(128) void gemm_proj(
    const float* __restrict__ A, const float* __restrict__ Wm)
{
    __shared__ float As[8][128];
    __shared__ float Bs[8][64];

    const int m0 = blockIdx.x * 128;
    const int n0 = blockIdx.y * 64;
    const int t  = threadIdx.x;
    const int ty = t >> 3;   // 0..15 (row group)
    const int tx = t & 7;    // 0..7  (col group)

    float acc[8][8];
    #pragma unroll
    for (int i = 0; i < 8; i++)
        #pragma unroll
        for (int j = 0; j < 8; j++) acc[i][j] = 0.f;

    for (int k0 = 0; k0 < Dd; k0 += 8) {
        // Load A tile: 128 rows x 8 k — thread t loads one row's 8 floats
        const float* ap = A + (size_t)(m0 + t) * Dd + k0;
        float4 a0 = *(const float4*)ap;
        float4 a1 = *(const float4*)(ap + 4);
        As[0][t] = a0.x; As[1][t] = a0.y; As[2][t] = a0.z; As[3][t] = a0.w;
        As[4][t] = a1.x; As[5][t] = a1.y; As[6][t] = a1.z; As[7][t] = a1.w;
        // Load B tile: 8 rows x 64 cols — thread loads one float4
        {
            int br = t >> 4;          // 0..7
            int bc = (t & 15) << 2;   // 0..60
            *(float4*)&Bs[br][bc] =
                *(const float4*)(Wm + (size_t)(k0 + br) * HC + n0 + bc);
        }
        __syncthreads();

        #pragma unroll
        for (int k = 0; k < 8; k++) {
            float af[8], bf[8];
            *(float4*)(af)     = *(const float4*)&As[k][ty * 8];
            *(float4*)(af + 4) = *(const float4*)&As[k][ty * 8 + 4];
            *(float4*)(bf)     = *(const float4*)&Bs[k][tx * 8];
            *(float4*)(bf + 4) = *(const float4*)&Bs[k][tx * 8 + 4];
            #pragma unroll
            for (int i = 0; i < 8; i++)
                #pragma unroll
                for (int j = 0; j < 8; j++)
                    acc[i][j] += af[i] * bf[j];
        }
        __syncthreads();
    }

    #pragma unroll
    for (int i = 0; i < 8; i++) {
        float* op = g_X + (size_t)(m0 + ty * 8 + i) * HC + n0 + tx * 8;
        *(float4*)op       = make_float4(acc[i][0], acc[i][1], acc[i][2], acc[i][3]);
        *(float4*)(op + 4) = make_float4(acc[i][4], acc[i][5], acc[i][6], acc[i][7]);
    }
}

// ---------------------------------------------------------------------------
// Kernel 2: per-node attention scores a_src/a_dst [B,N,H]
// One thread per (b,n,h); 64-length dots, fully unrolled float4.
// ---------------------------------------------------------------------------
__global__ __launch_bounds__(256) void att_scores(
    const float* __restrict__ att_src, const float* __restrict__ att_dst)
{
    int idx = blockIdx.x * blockDim.x + threadIdx.x;
    if (idx >= Bz * Nn * Hh) return;
    int h  = idx & 7;
    int bn = idx >> 3;
    const float* xp = g_X + (size_t)bn * HC + h * Cc;
    const float* ws = att_src + h * Cc;
    const float* wd = att_dst + h * Cc;
    float s = 0.f, d = 0.f;
    #pragma unroll
    for (int c = 0; c < Cc; c += 4) {
        float4 xv = *(const float4*)(xp + c);
        float4 sv = *(const float4*)(ws + c);
        float4 dv = *(const float4*)(wd + c);
        s += xv.x * sv.x + xv.y * sv.y + xv.z * sv.z + xv.w * sv.w;
        d += xv.x * dv.x + xv.y * dv.y + xv.z * dv.z + xv.w * dv.w;
    }
    g_asrc[idx] = s;
    g_adst[idx] = d;
}

// ---------------------------------------------------------------------------
// Kernel 3: fused masked-softmax aggregation + ELU epilogue.
// Block handles (b, 64-target tile, 2 heads). Streams sources i in tiles of 16.
// No online-max needed (logits bounded): out = (sum e*x) / (sum e).
// GEMM phase: 8j x 8c register tiles -> FMA-pipe bound by design.
// ---------------------------------------------------------------------------
#define TJ 64
#define TI 16

__global__ __launch_bounds__(128, 4) void gat_agg(
    const int* __restrict__ adj, const float* __restrict__ bias,
    float* __restrict__ out)
{
    __shared__ float es[TI][2][68];   // [i_local][head_local][j] (+pad: conflict-free frag reads)
    __shared__ float xs[TI][128];     // [i_local][2 heads * 64 c]
    __shared__ float adsts[2][TJ];
    __shared__ float ls[2][TJ];

    const int b  = blockIdx.z;
    const int h0 = blockIdx.y * 2;
    const int j0 = blockIdx.x * TJ;
    const int t  = threadIdx.x;

    // GEMM-phase identity: 8 j-groups x 16 c-groups, 8x8 tile each
    const int jg   = t >> 4;       // 0..7
    const int cg   = t & 15;       // 0..15 (spans 128 hc columns)
    const int hloc = cg >> 3;      // which of the 2 heads my c-columns belong to

    // Phase-1 identity: one (j, head) per thread
    const int pj = t & 63;
    const int ph = t >> 6;

    adsts[ph][pj] = g_adst[((size_t)b * Nn + j0 + pj) * Hh + h0 + ph];
    __syncthreads();
    const float my_adst = adsts[ph][pj];
    float lsum = 0.f;

    float acc[8][8];
    #pragma unroll
    for (int i = 0; i < 8; i++)
        #pragma unroll
        for (int j = 0; j < 8; j++) acc[i][j] = 0.f;

    const int* adjcol = adj + (size_t)b * Nn * Nn + j0;

    for (int i0 = 0; i0 < Nn; i0 += TI) {
        // ---- Phase 1: edge weights e = mask ? exp(leaky_relu(a_src+a_dst)) : 0
        #pragma unroll 4
        for (int il = 0; il < TI; il++) {
            int   i   = i0 + il;
            int   av  = adjcol[(size_t)i * Nn + pj];
            float asr = g_asrc[((size_t)b * Nn + i) * Hh + h0 + ph];
            float lg  = asr + my_adst;
            lg = (lg > 0.f) ? lg : 0.2f * lg;
            float e = ((av != 0) || (i == j0 + pj)) ? fexp(lg) : 0.f;
            es[il][ph][pj] = e;
            lsum += e;   // this thread owns (pj, ph) across all i -> exact l
        }
        // ---- Load x tile: 16 rows x 128 hc (coalesced float4)
        {
            const float* xbase = g_X + ((size_t)b * Nn + i0) * HC + h0 * Cc;
            #pragma unroll
            for (int u = 0; u < 4; u++) {
                int lin = u * 128 + t;      // float4 index, 0..511
                int il  = lin >> 5;         // 32 float4 per 128-wide row
                int hc4 = lin & 31;
                *(float4*)&xs[il][hc4 << 2] =
                    *(const float4*)(xbase + (size_t)il * HC + (hc4 << 2));
            }
        }
        __syncthreads();

        // ---- Phase 2: acc[j][c] += e[i][j] * x[i][c]  (64 FMA / 64B LDS per thread)
        #pragma unroll
        for (int il = 0; il < TI; il++) {
            float ef[8], xf[8];
            *(float4*)(ef)     = *(const float4*)&es[il][hloc][(jg << 3)];
            *(float4*)(ef + 4) = *(const float4*)&es[il][hloc][(jg << 3) + 4];
            *(float4*)(xf)     = *(const float4*)&xs[il][(cg << 3)];
            *(float4*)(xf + 4) = *(const float4*)&xs[il][(cg << 3) + 4];
            #pragma unroll
            for (int jj = 0; jj < 8; jj++)
                #pragma unroll
                for (int cc = 0; cc < 8; cc++)
                    acc[jj][cc] += ef[jj] * xf[cc];
        }
        __syncthreads();
    }

    // ---- Publish softmax denominators
    ls[ph][pj] = lsum;
    __syncthreads();

    // ---- Epilogue: normalize, +bias, ELU, store
    #pragma unroll
    for (int jj = 0; jj < 8; jj++) {
        int   j   = j0 + (jg << 3) + jj;
        float inv = 1.0f / ls[hloc][(jg << 3) + jj];
        float ov[8];
        #pragma unroll
        for (int cc = 0; cc < 8; cc++) {
            int   col = h0 * Cc + (cg << 3) + cc;
            float v   = acc[jj][cc] * inv + bias[col];
            ov[cc] = (v > 0.f) ? v : expm1f(v);
        }
        float* op = out + ((size_t)b * Nn + j) * HC + h0 * Cc + (cg << 3);
        *(float4*)op       = make_float4(ov[0], ov[1], ov[2], ov[3]);
        *(float4*)(op + 4) = make_float4(ov[4], ov[5], ov[6], ov[7]);
    }
}

// ---------------------------------------------------------------------------
// Launch
// ---------------------------------------------------------------------------
extern "C" void kernel_launch(void* const* d_in, const int* in_sizes, int n_in,
                              void* d_out, int out_size)
{
    const float* feats   = (const float*)d_in[0];  // [B,N,D]
    const int*   adj     = (const int*)  d_in[1];  // [B,N,N]
    const float* W       = (const float*)d_in[2];  // [D,HC]
    const float* att_src = (const float*)d_in[3];  // [H,C]
    const float* att_dst = (const float*)d_in[4];  // [H,C]
    const float* bias    = (const float*)d_in[5];  // [HC]
    float*       out     = (float*)d_out;          // [B,N,HC]

    (void)in_sizes; (void)n_in; (void)out_size;

    // 1) projection GEMM -> g_X
    gemm_proj<<<dim3((Bz * Nn) / 128, HC / 64), 128>>>(feats, W);
    // 2) attention scores -> g_asrc / g_adst
    att_scores<<<(Bz * Nn * Hh + 255) / 256, 256>>>(att_src, att_dst);
    // 3) fused masked-softmax aggregation + ELU -> out
    gat_agg<<<dim3(Nn / TJ, Hh / 2, Bz), 128>>>(adj, bias, out);
}

// round 5
// speedup vs baseline: 1.7758x; 1.7729x over previous
#include <cuda_runtime.h>
#include <cstdint>
#include <math.h>

#define Bz 4
#define Nn 2048
#define Dd 512
#define Hh 8
#define Cc 64
#define HC 512

// ---------------- device scratch ----------------
__device__ float g_X [(size_t)Bz * Nn * HC];   // projected features [B,N,HC]
__device__ float g_XT[(size_t)Bz * HC * Nn];   // transposed + tf32-rounded [B,HC,N]
__device__ float g_Es [(size_t)Bz * Nn * Hh];
__device__ float g_Es2[(size_t)Bz * Nn * Hh];
__device__ float g_Ed [(size_t)Bz * Nn * Hh];
__device__ float g_Ed2[(size_t)Bz * Nn * Hh];

// ---------------- helpers ----------------
__device__ __forceinline__ uint32_t smem_u32(const void* p) {
    uint32_t a;
    asm("{ .reg .u64 t; cvta.to.shared.u64 t, %1; cvt.u32.u64 %0, t; }"
        : "=r"(a) : "l"(p));
    return a;
}
// cvt.rna.tf32.f32 requires a .b32 destination register (ptxas rejects .f32)
__device__ __forceinline__ float tf32r(float x) {
    uint32_t r;
    asm("cvt.rna.tf32.f32 %0, %1;" : "=r"(r) : "f"(x));
    return __uint_as_float(r);
}
__device__ __forceinline__ void sts64f(uint32_t a, float2 v) {
    asm volatile("st.shared.v2.f32 [%0], {%1,%2};"
                 :: "r"(a), "f"(v.x), "f"(v.y) : "memory");
}
__device__ __forceinline__ void sts128f(uint32_t a, float4 v) {
    asm volatile("st.shared.v4.f32 [%0], {%1,%2,%3,%4};"
                 :: "r"(a), "f"(v.x), "f"(v.y), "f"(v.z), "f"(v.w) : "memory");
}
__device__ __forceinline__ uint2 lds64u(uint32_t a) {
    uint2 v;
    asm volatile("ld.shared.v2.u32 {%0,%1}, [%2];"
                 : "=r"(v.x), "=r"(v.y) : "r"(a));
    return v;
}

// legacy tensor-core mma (sm_80+ ISA; accepted by ptxas on sm_100 base target)
__device__ __forceinline__ void mma8(float* d,
                                     uint32_t a0, uint32_t a1, uint32_t a2, uint32_t a3,
                                     uint32_t b0, uint32_t b1) {
    asm volatile(
        "mma.sync.aligned.m16n8k8.row.col.f32.tf32.tf32.f32 "
        "{%0,%1,%2,%3}, {%4,%5,%6,%7}, {%8,%9}, {%0,%1,%2,%3};"
        : "+f"(d[0]), "+f"(d[1]), "+f"(d[2]), "+f"(d[3])
        : "r"(a0), "r"(a1), "r"(a2), "r"(a3), "r"(b0), "r"(b1));
}

// ---------------- fast exp (FFMA-only) ----------------
__device__ __forceinline__ float fexp(float x) {
    const float LOG2E = 1.4426950408889634f;
    float t = x * LOG2E;
    float z = t + 12582912.0f;
    int   n = __float_as_int(z) - 0x4B400000;
    float r = z - 12582912.0f;
    float f = t - r;
    float u = f * 0.69314718056f;
    float p = 8.3333333e-3f;
    p = p * u + 4.1666667e-2f;
    p = p * u + 1.6666667e-1f;
    p = p * u + 0.5f;
    p = p * u + 1.0f;
    p = p * u + 1.0f;
    return p * __int_as_float((n + 127) << 23);
}

// ---------------------------------------------------------------------------
// Kernel 1: projection GEMM (fp32, proven; round-6 target for mma conversion)
// ---------------------------------------------------------------------------
__global__ __launch_bounds__(128) void gemm_proj(
    const float* __restrict__ A, const float* __restrict__ Wm)
{
    __shared__ float As[8][128];
    __shared__ float Bs[8][64];

    const int m0 = blockIdx.x * 128;
    const int n0 = blockIdx.y * 64;
    const int t  = threadIdx.x;
    const int ty = t >> 3;
    const int tx = t & 7;

    float acc[8][8];
    #pragma unroll
    for (int i = 0; i < 8; i++)
        #pragma unroll
        for (int j = 0; j < 8; j++) acc[i][j] = 0.f;

    for (int k0 = 0; k0 < Dd; k0 += 8) {
        const float* ap = A + (size_t)(m0 + t) * Dd + k0;
        float4 a0 = *(const float4*)ap;
        float4 a1 = *(const float4*)(ap + 4);
        As[0][t] = a0.x; As[1][t] = a0.y; As[2][t] = a0.z; As[3][t] = a0.w;
        As[4][t] = a1.x; As[5][t] = a1.y; As[6][t] = a1.z; As[7][t] = a1.w;
        {
            int br = t >> 4;
            int bc = (t & 15) << 2;
            *(float4*)&Bs[br][bc] =
                *(const float4*)(Wm + (size_t)(k0 + br) * HC + n0 + bc);
        }
        __syncthreads();
        #pragma unroll
        for (int k = 0; k < 8; k++) {
            float af[8], bf[8];
            *(float4*)(af)     = *(const float4*)&As[k][ty * 8];
            *(float4*)(af + 4) = *(const float4*)&As[k][ty * 8 + 4];
            *(float4*)(bf)     = *(const float4*)&Bs[k][tx * 8];
            *(float4*)(bf + 4) = *(const float4*)&Bs[k][tx * 8 + 4];
            #pragma unroll
            for (int i = 0; i < 8; i++)
                #pragma unroll
                for (int j = 0; j < 8; j++)
                    acc[i][j] += af[i] * bf[j];
        }
        __syncthreads();
    }
    #pragma unroll
    for (int i = 0; i < 8; i++) {
        float* op = g_X + (size_t)(m0 + ty * 8 + i) * HC + n0 + tx * 8;
        *(float4*)op       = make_float4(acc[i][0], acc[i][1], acc[i][2], acc[i][3]);
        *(float4*)(op + 4) = make_float4(acc[i][4], acc[i][5], acc[i][6], acc[i][7]);
    }
}

// ---------------------------------------------------------------------------
// Kernel 2: transpose g_X -> g_XT [B,HC,N], tf32-rounded (rna)
// ---------------------------------------------------------------------------
__global__ __launch_bounds__(256) void xpose() {
    __shared__ float ts[32][33];
    const int b  = blockIdx.z;
    const int n0 = blockIdx.x << 5;
    const int c0 = blockIdx.y << 5;
    const int r  = threadIdx.x >> 5;
    const int cl = threadIdx.x & 31;

    #pragma unroll
    for (int rr = 0; rr < 32; rr += 8)
        ts[r + rr][cl] = g_X[((size_t)b * Nn + n0 + r + rr) * HC + c0 + cl];
    __syncthreads();
    #pragma unroll
    for (int rr = 0; rr < 32; rr += 8)
        g_XT[((size_t)b * HC + c0 + r + rr) * Nn + n0 + cl] = tf32r(ts[cl][r + rr]);
}

// ---------------------------------------------------------------------------
// Kernel 3: attention scores -> 4 exp tables.
// exp(leaky_relu(s+d)) == (Es*Ed > 1) ? Es*Ed : Es2*Ed2
// ---------------------------------------------------------------------------
__global__ __launch_bounds__(256) void att_prep(
    const float* __restrict__ att_src, const float* __restrict__ att_dst)
{
    int idx = blockIdx.x * blockDim.x + threadIdx.x;
    if (idx >= Bz * Nn * Hh) return;
    int h  = idx & 7;
    int bn = idx >> 3;
    const float* xp = g_X + (size_t)bn * HC + h * Cc;
    const float* ws = att_src + h * Cc;
    const float* wd = att_dst + h * Cc;
    float s = 0.f, d = 0.f;
    #pragma unroll
    for (int c = 0; c < Cc; c += 4) {
        float4 xv = *(const float4*)(xp + c);
        float4 sv = *(const float4*)(ws + c);
        float4 dv = *(const float4*)(wd + c);
        s += xv.x * sv.x + xv.y * sv.y + xv.z * sv.z + xv.w * sv.w;
        d += xv.x * dv.x + xv.y * dv.y + xv.z * dv.z + xv.w * dv.w;
    }
    g_Es [idx] = fexp(s);
    g_Es2[idx] = fexp(0.2f * s);
    g_Ed [idx] = fexp(d);
    g_Ed2[idx] = fexp(0.2f * d);
}

// ---------------------------------------------------------------------------
// Kernel 4: fused masked-softmax aggregation on tensor cores (mma.sync tf32).
// Block = (b, 2 heads, 128 j). K = 2048 sources in 32-i chunks.
// SMEM fragment-ordered staging: consumers do conflict-free ld.shared.v2.
//   A (e) frags:  [head][tw*2+mt][ks*2+rh] regions of 64 floats;
//                 granule (8B) = (row^s)*4 + (q^s), s = mt*2+rh  (XOR swizzle
//                 -> producer STS.64 lands exactly 2 threads/bank-pair).
//   B (xT) frags: [head][nt*4+ks][lane] float2 -> lane-linear.
// ---------------------------------------------------------------------------
#define AF_OFF 0       // 8192 floats
#define BF_OFF 8192    // 4096 floats
#define ES_OFF 12288   // 128 floats: [var(2)][head(2)][ii(32)]
#define LS_OFF 12416   // 256 floats
#define SM_FLOATS 12672

__global__ void __launch_bounds__(256, 2) gat_agg_mma(
    const int* __restrict__ adj, const float* __restrict__ bias,
    float* __restrict__ out)
{
    extern __shared__ float sm[];
    const uint32_t sb = smem_u32(sm);

    const int t  = threadIdx.x;
    const int b  = blockIdx.z;
    const int h0 = blockIdx.y * 2;
    const int j0 = blockIdx.x * 128;

    // producer identity (edge weights): one (j, head) per thread
    const int pj = t & 127, phead = t >> 7;
    const int tw = pj >> 5, mt_p = (pj >> 4) & 1, rh_p = (pj >> 3) & 1;
    const int row_p = pj & 7, s_p = mt_p * 2 + rh_p;

    // B-copy identity
    const int bhead = t >> 7, bc = (t >> 1) & 63, bksh = t & 1;

    // consumer identity
    const int wid = t >> 5, lane = t & 31;
    const int chead = wid >> 2, ctw = wid & 3;
    const int g = lane >> 2, tg = lane & 3;

    const size_t bn0 = (size_t)b * Nn;
    const float ed  = g_Ed [(bn0 + j0 + pj) * Hh + h0 + phead];
    const float ed2 = g_Ed2[(bn0 + j0 + pj) * Hh + h0 + phead];
    const int   diag = j0 + pj;
    const int*  adjp = adj + (size_t)b * Nn * Nn + j0 + pj;

    float acc[2][8][4];
    #pragma unroll
    for (int m = 0; m < 2; m++)
        #pragma unroll
        for (int n = 0; n < 8; n++)
            #pragma unroll
            for (int r = 0; r < 4; r++) acc[m][n][r] = 0.f;

    // precomputed base addresses (bytes)
    const uint32_t afw = sb + (AF_OFF + phead * 4096 +
                               ((tw * 2 + mt_p) * 8 + rh_p) * 64 +
                               ((row_p ^ s_p) * 4) * 2) * 4u;   // + ks*512 + (q^s)*8
    const float* xtbase = g_XT + ((size_t)b * HC + (size_t)(h0 + bhead) * Cc + bc) * Nn;
    const uint32_t bfw = sb + (BF_OFF + bhead * 2048 +
                               (bc >> 3) * 256 + (bc & 7) * 8) * 4u;  // + ks*256B

    float lsum = 0.f;

    for (int ch = 0; ch < 64; ++ch) {
        const int i0 = ch << 5;

        // ---- stage Es / Es2 for this chunk
        if (t < 128) {
            int var = t >> 6, hh = (t >> 5) & 1, ii = t & 31;
            const float* p = var ? g_Es2 : g_Es;
            sm[ES_OFF + t] = p[(bn0 + i0 + ii) * Hh + h0 + hh];
        }
        __syncthreads();   // ES visible; previous chunk fully consumed

        // ---- produce B fragments (xT copy, fragment-ordered)
        #pragma unroll
        for (int kk = 0; kk < 2; kk++) {
            const int ks = bksh * 2 + kk;
            const float* src = xtbase + i0 + ks * 8;
            float4 v0 = *(const float4*)src;
            float4 v1 = *(const float4*)(src + 4);
            const uint32_t ad = bfw + (uint32_t)ks * 256u;
            sts128f(ad,       make_float4(v0.x, v1.x, v0.y, v1.y));
            sts128f(ad + 16u, make_float4(v0.z, v1.z, v0.w, v1.w));
        }

        // ---- produce A fragments (edge weights)
        {
            const float* ES0 = sm + ES_OFF + phead * 32;
            const float* ES2 = sm + ES_OFF + 64 + phead * 32;
            #pragma unroll
            for (int ks = 0; ks < 4; ks++) {
                float4 elo  = *(const float4*)(ES0 + ks * 8);
                float4 ehi  = *(const float4*)(ES0 + ks * 8 + 4);
                float4 e2lo = *(const float4*)(ES2 + ks * 8);
                float4 e2hi = *(const float4*)(ES2 + ks * 8 + 4);
                const int ib = i0 + ks * 8;
                int a[8];
                #pragma unroll
                for (int u = 0; u < 8; u++) a[u] = adjp[(size_t)(ib + u) * Nn];
                const uint32_t ad = afw + (uint32_t)ks * 512u;
                const float* felo  = (const float*)&elo;
                const float* fehi  = (const float*)&ehi;
                const float* fe2lo = (const float*)&e2lo;
                const float* fe2hi = (const float*)&e2hi;
                #pragma unroll
                for (int q = 0; q < 4; q++) {
                    float ma  = felo[q] * ed;
                    float alt = fe2lo[q] * ed2;
                    float e0 = (ma > 1.f) ? ma : alt;
                    e0 = ((a[q] != 0) || (ib + q == diag)) ? e0 : 0.f;
                    e0 = tf32r(e0);
                    ma  = fehi[q] * ed;
                    alt = fe2hi[q] * ed2;
                    float e1 = (ma > 1.f) ? ma : alt;
                    e1 = ((a[q + 4] != 0) || (ib + q + 4 == diag)) ? e1 : 0.f;
                    e1 = tf32r(e1);
                    lsum += e0 + e1;
                    sts64f(ad + (uint32_t)((q ^ s_p) * 8), make_float2(e0, e1));
                }
            }
        }
        __syncthreads();   // fragments visible

        // ---- consume: 64 HMMA per warp
        #pragma unroll
        for (int ks = 0; ks < 4; ks++) {
            uint2 ub[8];
            #pragma unroll
            for (int nt = 0; nt < 8; nt++)
                ub[nt] = lds64u(sb + (BF_OFF + chead * 2048 +
                                      (nt * 4 + ks) * 64 + lane * 2) * 4u);
            #pragma unroll
            for (int mt = 0; mt < 2; mt++) {
                const int s0 = mt * 2, s1 = mt * 2 + 1;
                uint2 a02 = lds64u(sb + (AF_OFF + chead * 4096 +
                                         ((ctw * 2 + mt) * 8 + ks * 2 + 0) * 64 +
                                         ((g ^ s0) * 4 + (tg ^ s0)) * 2) * 4u);
                uint2 a13 = lds64u(sb + (AF_OFF + chead * 4096 +
                                         ((ctw * 2 + mt) * 8 + ks * 2 + 1) * 64 +
                                         ((g ^ s1) * 4 + (tg ^ s1)) * 2) * 4u);
                #pragma unroll
                for (int nt = 0; nt < 8; nt++)
                    mma8(acc[mt][nt], a02.x, a13.x, a02.y, a13.y,
                         ub[nt].x, ub[nt].y);
            }
        }
        // no sync here: next iteration's post-ES sync orders consume vs produce
    }

    // ---- softmax denominators
    sm[LS_OFF + phead * 128 + pj] = lsum;
    __syncthreads();

    // ---- epilogue: normalize, +bias, ELU, store (direct float2 STG)
    const float* bp = bias + (size_t)(h0 + chead) * Cc;
    #pragma unroll
    for (int mt = 0; mt < 2; mt++) {
        const int r0 = ctw * 32 + mt * 16 + g;
        const int r1 = r0 + 8;
        const float inv0 = 1.f / sm[LS_OFF + chead * 128 + r0];
        const float inv1 = 1.f / sm[LS_OFF + chead * 128 + r1];
        float* o0 = out + (bn0 + j0 + r0) * HC + (size_t)(h0 + chead) * Cc;
        float* o1 = out + (bn0 + j0 + r1) * HC + (size_t)(h0 + chead) * Cc;
        #pragma unroll
        for (int nt = 0; nt < 8; nt++) {
            const int c = nt * 8 + tg * 2;
            const float b0v = bp[c], b1v = bp[c + 1];
            float v0 = acc[mt][nt][0] * inv0 + b0v;
            float v1 = acc[mt][nt][1] * inv0 + b1v;
            float v2 = acc[mt][nt][2] * inv1 + b0v;
            float v3 = acc[mt][nt][3] * inv1 + b1v;
            v0 = v0 > 0.f ? v0 : (fexp(v0) - 1.f);
            v1 = v1 > 0.f ? v1 : (fexp(v1) - 1.f);
            v2 = v2 > 0.f ? v2 : (fexp(v2) - 1.f);
            v3 = v3 > 0.f ? v3 : (fexp(v3) - 1.f);
            *(float2*)(o0 + c) = make_float2(v0, v1);
            *(float2*)(o1 + c) = make_float2(v2, v3);
        }
    }
}

// ---------------------------------------------------------------------------
extern "C" void kernel_launch(void* const* d_in, const int* in_sizes, int n_in,
                              void* d_out, int out_size)
{
    const float* feats   = (const float*)d_in[0];
    const int*   adj     = (const int*)  d_in[1];
    const float* W       = (const float*)d_in[2];
    const float* att_src = (const float*)d_in[3];
    const float* att_dst = (const float*)d_in[4];
    const float* bias    = (const float*)d_in[5];
    float*       out     = (float*)d_out;
    (void)in_sizes; (void)n_in; (void)out_size;

    static bool attr_set = false;
    if (!attr_set) {
        cudaFuncSetAttribute(gat_agg_mma,
                             cudaFuncAttributeMaxDynamicSharedMemorySize,
                             SM_FLOATS * 4);
        attr_set = true;
    }

    gemm_proj<<<dim3((Bz * Nn) / 128, HC / 64), 128>>>(feats, W);
    xpose<<<dim3(Nn / 32, HC / 32, Bz), 256>>>();
    att_prep<<<(Bz * Nn * Hh + 255) / 256, 256>>>(att_src, att_dst);
    gat_agg_mma<<<dim3(Nn / 128, Hh / 2, Bz), 256, SM_FLOATS * 4>>>(adj, bias, out);
}

// round 6
// speedup vs baseline: 2.7461x; 1.5464x over previous
#include <cuda_runtime.h>
#include <cstdint>
#include <math.h>

#define Bz 4
#define Nn 2048
#define Dd 512
#define Hh 8
#define Cc 64
#define HC 512

// ---------------- device scratch ----------------
__device__ float g_X [(size_t)Bz * Nn * HC];    // projected features [B,N,HC]
__device__ float g_XT[(size_t)Bz * HC * Nn];    // transposed, tf32-rounded, i-pair-interleaved
__device__ float g_Fr[(size_t)Bz * Nn * Dd];    // tf32-rounded feats
__device__ float g_Wr[(size_t)Dd * HC];         // tf32-rounded W
__device__ float g_EsT [(size_t)Bz * Hh * Nn];  // exp tables, [b][h][n]
__device__ float g_Es2T[(size_t)Bz * Hh * Nn];
__device__ float g_EdT [(size_t)Bz * Hh * Nn];
__device__ float g_Ed2T[(size_t)Bz * Hh * Nn];
__device__ uint32_t g_adjT[(size_t)Bz * Nn * 64]; // adjacency bits: [b][j][i/32]

// ---------------- helpers ----------------
__device__ __forceinline__ uint32_t smem_u32(const void* p) {
    uint32_t a;
    asm("{ .reg .u64 t; cvta.to.shared.u64 t, %1; cvt.u32.u64 %0, t; }"
        : "=r"(a) : "l"(p));
    return a;
}
__device__ __forceinline__ float tf32r(float x) {
    uint32_t r;
    asm("cvt.rna.tf32.f32 %0, %1;" : "=r"(r) : "f"(x));
    return __uint_as_float(r);
}
__device__ __forceinline__ void sts64f(uint32_t a, float2 v) {
    asm volatile("st.shared.v2.f32 [%0], {%1,%2};"
                 :: "r"(a), "f"(v.x), "f"(v.y) : "memory");
}
__device__ __forceinline__ uint2 lds64u(uint32_t a) {
    uint2 v;
    asm volatile("ld.shared.v2.u32 {%0,%1}, [%2];"
                 : "=r"(v.x), "=r"(v.y) : "r"(a));
    return v;
}
__device__ __forceinline__ uint32_t lds32u(uint32_t a) {
    uint32_t v;
    asm volatile("ld.shared.u32 %0, [%1];" : "=r"(v) : "r"(a));
    return v;
}
__device__ __forceinline__ float4 lds128(uint32_t a) {
    float4 v;
    asm volatile("ld.shared.v4.f32 {%0,%1,%2,%3}, [%4];"
                 : "=f"(v.x), "=f"(v.y), "=f"(v.z), "=f"(v.w) : "r"(a));
    return v;
}

#define CP_ASYNC16(dst, src) \
    asm volatile("cp.async.cg.shared.global [%0], [%1], 16;" \
                 :: "r"(dst), "l"(src) : "memory")
#define CP_ASYNC4(dst, src) \
    asm volatile("cp.async.ca.shared.global [%0], [%1], 4;" \
                 :: "r"(dst), "l"(src) : "memory")
#define CP_COMMIT()  asm volatile("cp.async.commit_group;" ::: "memory")
#define CP_WAIT2()   asm volatile("cp.async.wait_group 2;" ::: "memory")

// legacy tensor-core mma (sm_80+ ISA; accepted on sm_100 base target)
__device__ __forceinline__ void mma8(float* d,
                                     uint32_t a0, uint32_t a1, uint32_t a2, uint32_t a3,
                                     uint32_t b0, uint32_t b1) {
    asm volatile(
        "mma.sync.aligned.m16n8k8.row.col.f32.tf32.tf32.f32 "
        "{%0,%1,%2,%3}, {%4,%5,%6,%7}, {%8,%9}, {%0,%1,%2,%3};"
        : "+f"(d[0]), "+f"(d[1]), "+f"(d[2]), "+f"(d[3])
        : "r"(a0), "r"(a1), "r"(a2), "r"(a3), "r"(b0), "r"(b1));
}

// ---------------- fast exp (FFMA-only) ----------------
__device__ __forceinline__ float fexp(float x) {
    const float LOG2E = 1.4426950408889634f;
    float t = x * LOG2E;
    float z = t + 12582912.0f;
    int   n = __float_as_int(z) - 0x4B400000;
    float r = z - 12582912.0f;
    float f = t - r;
    float u = f * 0.69314718056f;
    float p = 8.3333333e-3f;
    p = p * u + 4.1666667e-2f;
    p = p * u + 1.6666667e-1f;
    p = p * u + 0.5f;
    p = p * u + 1.0f;
    p = p * u + 1.0f;
    return p * __int_as_float((n + 127) << 23);
}

// ---------------------------------------------------------------------------
// Kernel 0: tf32-round copies (rna) so proj MMA sees rna-rounded inputs
// ---------------------------------------------------------------------------
__global__ __launch_bounds__(256) void round_copy(
    const float* __restrict__ src, float* __restrict__ dst, int n4)
{
    int i = blockIdx.x * blockDim.x + threadIdx.x;
    if (i >= n4) return;
    float4 v = ((const float4*)src)[i];
    v.x = tf32r(v.x); v.y = tf32r(v.y); v.z = tf32r(v.z); v.w = tf32r(v.w);
    ((float4*)dst)[i] = v;
}

// ---------------------------------------------------------------------------
// Kernel 1: adjacency -> transposed bitmask  g_adjT[b][j][iw]
// ---------------------------------------------------------------------------
__global__ __launch_bounds__(256) void pack_adjT(const int* __restrict__ adj)
{
    const int b  = blockIdx.z;
    const int iw = blockIdx.y;
    const int j  = blockIdx.x * 256 + threadIdx.x;
    const int* p = adj + ((size_t)b * Nn + (size_t)iw * 32) * Nn + j;
    uint32_t w = 0;
    #pragma unroll
    for (int bit = 0; bit < 32; ++bit)
        w |= (p[(size_t)bit * Nn] != 0 ? 1u : 0u) << bit;
    g_adjT[((size_t)b * Nn + j) * 64 + iw] = w;
}

// ---------------------------------------------------------------------------
// Kernel 2: projection GEMM on tensor cores (mma.sync tf32, cp.async 4-stage)
// X[8192,512] = Fr[8192,512] @ Wr[512,512]; block tile 128x128, 8 warps.
// ---------------------------------------------------------------------------
#define PA_OFF 0u        // A stages: 4 x 128 rows x 20 floats (80B row) = 40960B
#define PB_OFF 40960u    // B stages: 4 x 16 rows x 136 floats (544B row) = 34816B
#define PROJ_SMEM 75776u

__global__ void __launch_bounds__(256, 2) gemm_proj_mma()
{
    extern __shared__ float sm[];
    const uint32_t sb = smem_u32(sm);

    const int t  = threadIdx.x;
    const int m0 = blockIdx.x * 128;
    const int n0 = blockIdx.y * 128;
    const int wid = t >> 5, lane = t & 31;
    const int wm = wid & 1, wn = wid >> 1;
    const int g = lane >> 2, tg = lane & 3;

    float acc[4][4][4];
    #pragma unroll
    for (int i = 0; i < 4; i++)
        #pragma unroll
        for (int j = 0; j < 4; j++)
            #pragma unroll
            for (int r = 0; r < 4; r++) acc[i][j][r] = 0.f;

    // cp.async bases (A: 512 granules, 2/thread; B: 512 granules, 2/thread)
    const float* asrc[2]; uint32_t adst[2];
    const float* bsrc[2]; uint32_t bdst[2];
    #pragma unroll
    for (int u = 0; u < 2; u++) {
        int gid = u * 256 + t;
        int ar = gid >> 2, ag = gid & 3;
        asrc[u] = g_Fr + (size_t)(m0 + ar) * Dd + ag * 4;     // + k0
        adst[u] = sb + PA_OFF + (uint32_t)(ar * 80 + ag * 16); // + buf*10240
        int br = gid >> 5, bg = gid & 31;
        bsrc[u] = g_Wr + (size_t)br * HC + n0 + bg * 4;       // + k0*HC
        bdst[u] = sb + PB_OFF + (uint32_t)(br * 544 + bg * 16);// + buf*8704
    }

    // prologue: stages 0..2
    #pragma unroll
    for (int s = 0; s < 3; s++) {
        #pragma unroll
        for (int u = 0; u < 2; u++) {
            CP_ASYNC16(adst[u] + s * 10240u, asrc[u] + s * 16);
            CP_ASYNC16(bdst[u] + s * 8704u,  bsrc[u] + (size_t)(s * 16) * HC);
        }
        CP_COMMIT();
    }

    for (int kc = 0; kc < 32; ++kc) {
        const int buf = kc & 3;
        CP_WAIT2();
        __syncthreads();
        if (kc < 29) {
            const int s = (kc + 3) & 3, k0 = (kc + 3) * 16;
            #pragma unroll
            for (int u = 0; u < 2; u++) {
                CP_ASYNC16(adst[u] + s * 10240u, asrc[u] + k0);
                CP_ASYNC16(bdst[u] + s * 8704u,  bsrc[u] + (size_t)k0 * HC);
            }
            CP_COMMIT();
        } else {
            CP_COMMIT();   // empty group keeps wait_group accounting uniform
        }

        const uint32_t Ab = sb + PA_OFF + buf * 10240u + (uint32_t)(wm * 64) * 80u;
        const uint32_t Bb = sb + PB_OFF + buf * 8704u + (uint32_t)(wn * 32) * 4u;

        #pragma unroll
        for (int ks = 0; ks < 2; ks++) {
            uint32_t a[4][4];
            #pragma unroll
            for (int mt = 0; mt < 4; mt++) {
                const uint32_t base = Ab + (uint32_t)((mt * 16 + g) * 80 + (ks * 8 + tg) * 4);
                a[mt][0] = lds32u(base);
                a[mt][1] = lds32u(base + 640u);        // +8 rows
                a[mt][2] = lds32u(base + 16u);         // +4 k
                a[mt][3] = lds32u(base + 656u);
            }
            uint2 bf[4];
            #pragma unroll
            for (int nt = 0; nt < 4; nt++) {
                const uint32_t base = Bb + (uint32_t)((ks * 8 + tg) * 544 + (nt * 8 + g) * 4);
                bf[nt].x = lds32u(base);
                bf[nt].y = lds32u(base + 2176u);       // +4 k-rows
            }
            #pragma unroll
            for (int mt = 0; mt < 4; mt++)
                #pragma unroll
                for (int nt = 0; nt < 4; nt++)
                    mma8(acc[mt][nt], a[mt][0], a[mt][1], a[mt][2], a[mt][3],
                         bf[nt].x, bf[nt].y);
        }
    }

    // epilogue
    #pragma unroll
    for (int mt = 0; mt < 4; mt++) {
        const int m = m0 + wm * 64 + mt * 16 + g;
        #pragma unroll
        for (int nt = 0; nt < 4; nt++) {
            const int n = n0 + wn * 32 + nt * 8 + tg * 2;
            *(float2*)(g_X + (size_t)m * HC + n)       = make_float2(acc[mt][nt][0], acc[mt][nt][1]);
            *(float2*)(g_X + (size_t)(m + 8) * HC + n) = make_float2(acc[mt][nt][2], acc[mt][nt][3]);
        }
    }
}

// ---------------------------------------------------------------------------
// Kernel 3: transpose g_X -> g_XT [B,HC,N], tf32-rounded, i-pair interleaved:
// within each 8-i group, position 2q holds i=q, 2q+1 holds i=q+4 -> B frags
// become adjacent pairs for ld.shared.v2.
// ---------------------------------------------------------------------------
__global__ __launch_bounds__(256) void xpose() {
    __shared__ float ts[32][33];
    const int b  = blockIdx.z;
    const int n0 = blockIdx.x << 5;
    const int c0 = blockIdx.y << 5;
    const int r  = threadIdx.x >> 5;
    const int cl = threadIdx.x & 31;

    #pragma unroll
    for (int rr = 0; rr < 32; rr += 8)
        ts[r + rr][cl] = g_X[((size_t)b * Nn + n0 + r + rr) * HC + c0 + cl];
    __syncthreads();
    const int perm = (cl & 24) | ((cl & 3) << 1) | ((cl >> 2) & 1);
    #pragma unroll
    for (int rr = 0; rr < 32; rr += 8)
        g_XT[((size_t)b * HC + c0 + r + rr) * Nn + n0 + perm] = tf32r(ts[cl][r + rr]);
}

// ---------------------------------------------------------------------------
// Kernel 4: attention scores -> 4 transposed exp tables [b][h][n].
// exp(leaky_relu(s+d)) == (Es*Ed > 1) ? Es*Ed : Es2*Ed2
// ---------------------------------------------------------------------------
__global__ __launch_bounds__(256) void att_prep(
    const float* __restrict__ att_src, const float* __restrict__ att_dst)
{
    int idx = blockIdx.x * blockDim.x + threadIdx.x;
    if (idx >= Bz * Nn * Hh) return;
    int h  = idx & 7;
    int bn = idx >> 3;
    int b  = bn >> 11;
    int n  = bn & 2047;
    const float* xp = g_X + (size_t)bn * HC + h * Cc;
    const float* ws = att_src + h * Cc;
    const float* wd = att_dst + h * Cc;
    float s = 0.f, d = 0.f;
    #pragma unroll
    for (int c = 0; c < Cc; c += 4) {
        float4 xv = *(const float4*)(xp + c);
        float4 sv = *(const float4*)(ws + c);
        float4 dv = *(const float4*)(wd + c);
        s += xv.x * sv.x + xv.y * sv.y + xv.z * sv.z + xv.w * sv.w;
        d += xv.x * dv.x + xv.y * dv.y + xv.z * dv.z + xv.w * dv.w;
    }
    size_t o = ((size_t)b * Hh + h) * Nn + n;
    g_EsT [o] = fexp(s);
    g_Es2T[o] = fexp(0.2f * s);
    g_EdT [o] = fexp(d);
    g_Ed2T[o] = fexp(0.2f * d);
}

// ---------------------------------------------------------------------------
// Kernel 5: fused masked-softmax aggregation (mma.sync tf32 + cp.async x4).
// Block = (b, 2 heads, 128 j); K=2048 sources in 32-i chunks.
// ---------------------------------------------------------------------------
#define XT_OFFB  0u        // 4 x 16384B (128 rows x 128B, 16B-granule XOR swizzle)
#define AF_OFFB  65536u    // A frags: 32768B (R5 layout)
#define ADJ_OFFB 98304u    // 4 x 512B (128 words: [j])
#define ES_OFFB  100352u   // 4 x 512B ([var2][hh2][32 floats])
#define LS_FIDX  25600     // float index of LS (byte 102400)
#define AGG_SMEM 103424u

__global__ void __launch_bounds__(256, 2) gat_agg_mma(
    const float* __restrict__ bias, float* __restrict__ out)
{
    extern __shared__ float sm[];
    const uint32_t sb = smem_u32(sm);

    const int t  = threadIdx.x;
    const int b  = blockIdx.z;
    const int h0 = blockIdx.y * 2;
    const int j0 = blockIdx.x * 128;

    // producer identity
    const int pj = t & 127, phead = t >> 7;
    const int tw = pj >> 5, mt_p = (pj >> 4) & 1, rh_p = (pj >> 3) & 1;
    const int row_p = pj & 7, s_p = mt_p * 2 + rh_p;
    // consumer identity
    const int wid = t >> 5, lane = t & 31;
    const int chead = wid >> 2, ctw = wid & 3;
    const int g = lane >> 2, tg = lane & 3;

    const size_t bn0 = (size_t)b * Nn;
    const float ed  = g_EdT [((size_t)b * Hh + h0 + phead) * Nn + j0 + pj];
    const float ed2 = g_Ed2T[((size_t)b * Hh + h0 + phead) * Nn + j0 + pj];
    const int diag = j0 + pj;
    const int diag_ch = diag >> 5;
    const uint32_t diag_bit = 1u << (diag & 31);

    float acc[2][8][4];
    #pragma unroll
    for (int m = 0; m < 2; m++)
        #pragma unroll
        for (int n = 0; n < 8; n++)
            #pragma unroll
            for (int r = 0; r < 4; r++) acc[m][n][r] = 0.f;

    // cp.async bases
    const float* xsrc[4]; uint32_t xdst[4];
    #pragma unroll
    for (int u = 0; u < 4; u++) {
        int gid = u * 256 + t;
        int row = gid >> 3, gr = gid & 7;
        int hh = row >> 6, c = row & 63;
        xsrc[u] = g_XT + ((size_t)b * HC + (size_t)(h0 + hh) * Cc + c) * Nn + gr * 4;
        xdst[u] = sb + XT_OFFB + (uint32_t)(row * 128 + ((gr ^ (row & 7)) << 4));
    }
    const uint32_t* ajsrc = g_adjT + (bn0 + j0 + (t & 127)) * 64;   // + ch (t<128)
    const float* essrc = nullptr; uint32_t esdst = 0;
    if (t >= 128 && t < 160) {
        int seg = (t - 128) >> 3, gi = t & 7;
        int var = seg >> 1, hh = seg & 1;
        const float* tbl = var ? g_Es2T : g_EsT;
        essrc = tbl + ((size_t)b * Hh + h0 + hh) * Nn + gi * 4;     // + i0
        esdst = sb + ES_OFFB + (uint32_t)(seg * 128 + gi * 16);
    }

    // A-frag producer/consumer byte bases (R5-proven layout)
    const uint32_t afw = sb + AF_OFFB +
        (uint32_t)(phead * 16384 + ((tw * 2 + mt_p) * 8 + rh_p) * 256 + (row_p ^ s_p) * 32);

    // prologue: stages 0..2
    #pragma unroll
    for (int s = 0; s < 3; s++) {
        #pragma unroll
        for (int u = 0; u < 4; u++) CP_ASYNC16(xdst[u] + s * 16384u, xsrc[u] + s * 32);
        if (t < 128) CP_ASYNC4(sb + ADJ_OFFB + s * 512u + (t << 2), ajsrc + s);
        if (t >= 128 && t < 160) CP_ASYNC16(esdst + s * 512u, essrc + s * 32);
        CP_COMMIT();
    }

    float lsum = 0.f;

    for (int ch = 0; ch < 64; ++ch) {
        const int buf = ch & 3;
        CP_WAIT2();
        __syncthreads();   // stage ch visible; consume(ch-1) done

        if (ch < 61) {
            const int s = ch + 3, sb4 = s & 3;
            #pragma unroll
            for (int u = 0; u < 4; u++) CP_ASYNC16(xdst[u] + sb4 * 16384u, xsrc[u] + s * 32);
            if (t < 128) CP_ASYNC4(sb + ADJ_OFFB + sb4 * 512u + (t << 2), ajsrc + s);
            if (t >= 128 && t < 160) CP_ASYNC16(esdst + sb4 * 512u, essrc + s * 32);
            CP_COMMIT();
        } else {
            CP_COMMIT();
        }

        // ---- produce A fragments from staged adj-bits + Es tables
        uint32_t w = lds32u(sb + ADJ_OFFB + buf * 512u + (uint32_t)(pj << 2));
        if (ch == diag_ch) w |= diag_bit;
        const uint32_t esb0 = sb + ES_OFFB + buf * 512u + (uint32_t)(phead * 128);
        const uint32_t esb2 = esb0 + 256u;

        #pragma unroll
        for (int ks = 0; ks < 4; ks++) {
            float4 elo  = lds128(esb0 + ks * 32);
            float4 ehi  = lds128(esb0 + ks * 32 + 16);
            float4 e2lo = lds128(esb2 + ks * 32);
            float4 e2hi = lds128(esb2 + ks * 32 + 16);
            const uint32_t wk = w >> (ks * 8);
            const uint32_t ad = afw + (uint32_t)(ks * 512);
            const float* fl  = (const float*)&elo;
            const float* fh  = (const float*)&ehi;
            const float* f2l = (const float*)&e2lo;
            const float* f2h = (const float*)&e2hi;
            #pragma unroll
            for (int q = 0; q < 4; q++) {
                float ma  = fl[q] * ed;
                float alt = f2l[q] * ed2;
                float e0 = (ma > 1.f) ? ma : alt;
                e0 = (wk & (1u << q)) ? e0 : 0.f;
                e0 = tf32r(e0);
                ma  = fh[q] * ed;
                alt = f2h[q] * ed2;
                float e1 = (ma > 1.f) ? ma : alt;
                e1 = (wk & (1u << (q + 4))) ? e1 : 0.f;
                e1 = tf32r(e1);
                lsum += e0 + e1;
                sts64f(ad + (uint32_t)((q ^ s_p) * 8), make_float2(e0, e1));
            }
        }
        __syncthreads();   // A frags visible

        // ---- consume: B frags straight from swizzled XT stage, A from frags
        const uint32_t xtb = sb + XT_OFFB + buf * 16384u + (uint32_t)(chead * 8192);
        #pragma unroll
        for (int ks = 0; ks < 4; ks++) {
            uint2 ub[8];
            #pragma unroll
            for (int nt = 0; nt < 8; nt++) {
                const int row = nt * 8 + g;
                const int g16 = (2 * ks + (tg >> 1)) ^ (row & 7);
                ub[nt] = lds64u(xtb + (uint32_t)(row * 128 + g16 * 16 + (tg & 1) * 8));
            }
            #pragma unroll
            for (int mt = 0; mt < 2; mt++) {
                const int s0 = mt * 2, s1 = mt * 2 + 1;
                uint2 a02 = lds64u(sb + AF_OFFB + (uint32_t)(chead * 16384 +
                                   ((ctw * 2 + mt) * 8 + ks * 2 + 0) * 256 +
                                   ((g ^ s0) * 4 + (tg ^ s0)) * 8));
                uint2 a13 = lds64u(sb + AF_OFFB + (uint32_t)(chead * 16384 +
                                   ((ctw * 2 + mt) * 8 + ks * 2 + 1) * 256 +
                                   ((g ^ s1) * 4 + (tg ^ s1)) * 8));
                #pragma unroll
                for (int nt = 0; nt < 8; nt++)
                    mma8(acc[mt][nt], a02.x, a13.x, a02.y, a13.y,
                         ub[nt].x, ub[nt].y);
            }
        }
    }

    // ---- softmax denominators
    sm[LS_FIDX + phead * 128 + pj] = lsum;
    __syncthreads();

    // ---- epilogue: normalize, +bias, ELU, store
    const float* bp = bias + (size_t)(h0 + chead) * Cc;
    #pragma unroll
    for (int mt = 0; mt < 2; mt++) {
        const int r0 = ctw * 32 + mt * 16 + g;
        const int r1 = r0 + 8;
        const float inv0 = 1.f / sm[LS_FIDX + chead * 128 + r0];
        const float inv1 = 1.f / sm[LS_FIDX + chead * 128 + r1];
        float* o0 = out + (bn0 + j0 + r0) * HC + (size_t)(h0 + chead) * Cc;
        float* o1 = out + (bn0 + j0 + r1) * HC + (size_t)(h0 + chead) * Cc;
        #pragma unroll
        for (int nt = 0; nt < 8; nt++) {
            const int c = nt * 8 + tg * 2;
            const float b0v = bp[c], b1v = bp[c + 1];
            float v0 = acc[mt][nt][0] * inv0 + b0v;
            float v1 = acc[mt][nt][1] * inv0 + b1v;
            float v2 = acc[mt][nt][2] * inv1 + b0v;
            float v3 = acc[mt][nt][3] * inv1 + b1v;
            v0 = v0 > 0.f ? v0 : (fexp(v0) - 1.f);
            v1 = v1 > 0.f ? v1 : (fexp(v1) - 1.f);
            v2 = v2 > 0.f ? v2 : (fexp(v2) - 1.f);
            v3 = v3 > 0.f ? v3 : (fexp(v3) - 1.f);
            *(float2*)(o0 + c) = make_float2(v0, v1);
            *(float2*)(o1 + c) = make_float2(v2, v3);
        }
    }
}

// ---------------------------------------------------------------------------
extern "C" void kernel_launch(void* const* d_in, const int* in_sizes, int n_in,
                              void* d_out, int out_size)
{
    const float* feats   = (const float*)d_in[0];
    const int*   adj     = (const int*)  d_in[1];
    const float* W       = (const float*)d_in[2];
    const float* att_src = (const float*)d_in[3];
    const float* att_dst = (const float*)d_in[4];
    const float* bias    = (const float*)d_in[5];
    float*       out     = (float*)d_out;
    (void)in_sizes; (void)n_in; (void)out_size;

    static bool attr_set = false;
    if (!attr_set) {
        cudaFuncSetAttribute(gat_agg_mma,
                             cudaFuncAttributeMaxDynamicSharedMemorySize, AGG_SMEM);
        cudaFuncSetAttribute(gemm_proj_mma,
                             cudaFuncAttributeMaxDynamicSharedMemorySize, PROJ_SMEM);
        attr_set = true;
    }

    float *dFr, *dWr;
    cudaGetSymbolAddress((void**)&dFr, g_Fr);
    cudaGetSymbolAddress((void**)&dWr, g_Wr);

    round_copy<<<(Bz * Nn * Dd / 4 + 255) / 256, 256>>>(feats, dFr, Bz * Nn * Dd / 4);
    round_copy<<<(Dd * HC / 4 + 255) / 256, 256>>>(W, dWr, Dd * HC / 4);
    pack_adjT<<<dim3(Nn / 256, 64, Bz), 256>>>(adj);
    gemm_proj_mma<<<dim3((Bz * Nn) / 128, HC / 128), 256, PROJ_SMEM>>>();
    xpose<<<dim3(Nn / 32, HC / 32, Bz), 256>>>();
    att_prep<<<(Bz * Nn * Hh + 255) / 256, 256>>>(att_src, att_dst);
    gat_agg_mma<<<dim3(Nn / 128, Hh / 2, Bz), 256, AGG_SMEM>>>(bias, out);
}

// round 7
// speedup vs baseline: 3.7009x; 1.3477x over previous
#include <cuda_runtime.h>
#include <cuda_fp16.h>
#include <cstdint>
#include <math.h>

#define Bz 4
#define Nn 2048
#define Dd 512
#define Hh 8
#define Cc 64
#define HC 512

#define THRESH 0.0183156393f   // e^-4: branch threshold for scaled Es tables

// ---------------- device scratch ----------------
__device__ float  g_X [(size_t)Bz * Nn * HC];    // projected features [B,N,HC]
__device__ __half g_XTh[(size_t)Bz * HC * Nn];   // transposed fp16, i-pair permuted
__device__ float  g_Fr[(size_t)Bz * Nn * Dd];    // tf32-rounded feats
__device__ float  g_Wr[(size_t)Dd * HC];         // tf32-rounded W
__device__ float  g_EsT [(size_t)Bz * Hh * Nn];  // exp(s-4)  [b][h][n]
__device__ float  g_Es2T[(size_t)Bz * Hh * Nn];  // exp(.2s-4)
__device__ float  g_EdT [(size_t)Bz * Hh * Nn];  // exp(d)
__device__ float  g_Ed2T[(size_t)Bz * Hh * Nn];  // exp(.2d)
__device__ uint32_t g_adjT[(size_t)Bz * Nn * 64]; // adjacency bits: [b][j][i/32]

// ---------------- helpers ----------------
__device__ __forceinline__ uint32_t smem_u32(const void* p) {
    uint32_t a;
    asm("{ .reg .u64 t; cvta.to.shared.u64 t, %1; cvt.u32.u64 %0, t; }"
        : "=r"(a) : "l"(p));
    return a;
}
__device__ __forceinline__ float tf32r(float x) {
    uint32_t r;
    asm("cvt.rna.tf32.f32 %0, %1;" : "=r"(r) : "f"(x));
    return __uint_as_float(r);
}
__device__ __forceinline__ uint2 lds64u(uint32_t a) {
    uint2 v;
    asm volatile("ld.shared.v2.u32 {%0,%1}, [%2];"
                 : "=r"(v.x), "=r"(v.y) : "r"(a));
    return v;
}
__device__ __forceinline__ float2 lds64f(uint32_t a) {
    float2 v;
    asm volatile("ld.shared.v2.f32 {%0,%1}, [%2];"
                 : "=f"(v.x), "=f"(v.y) : "r"(a));
    return v;
}
__device__ __forceinline__ uint32_t lds32u(uint32_t a) {
    uint32_t v;
    asm volatile("ld.shared.u32 %0, [%1];" : "=r"(v) : "r"(a));
    return v;
}
__device__ __forceinline__ void sts128u(uint32_t a, uint32_t v0, uint32_t v1,
                                        uint32_t v2, uint32_t v3) {
    asm volatile("st.shared.v4.u32 [%0], {%1,%2,%3,%4};"
                 :: "r"(a), "r"(v0), "r"(v1), "r"(v2), "r"(v3) : "memory");
}

#define CP_ASYNC16(dst, src) \
    asm volatile("cp.async.cg.shared.global [%0], [%1], 16;" \
                 :: "r"(dst), "l"(src) : "memory")
#define CP_ASYNC4(dst, src) \
    asm volatile("cp.async.ca.shared.global [%0], [%1], 4;" \
                 :: "r"(dst), "l"(src) : "memory")
#define CP_COMMIT()  asm volatile("cp.async.commit_group;" ::: "memory")
#define CP_WAIT2()   asm volatile("cp.async.wait_group 2;" ::: "memory")

// tf32 mma (proj kernel)
__device__ __forceinline__ void mma8(float* d,
                                     uint32_t a0, uint32_t a1, uint32_t a2, uint32_t a3,
                                     uint32_t b0, uint32_t b1) {
    asm volatile(
        "mma.sync.aligned.m16n8k8.row.col.f32.tf32.tf32.f32 "
        "{%0,%1,%2,%3}, {%4,%5,%6,%7}, {%8,%9}, {%0,%1,%2,%3};"
        : "+f"(d[0]), "+f"(d[1]), "+f"(d[2]), "+f"(d[3])
        : "r"(a0), "r"(a1), "r"(a2), "r"(a3), "r"(b0), "r"(b1));
}
// fp16 mma (agg kernel): same 10-bit mantissa as tf32, 2x rate
__device__ __forceinline__ void mma16(float* d,
                                      uint32_t a0, uint32_t a1, uint32_t a2, uint32_t a3,
                                      uint32_t b0, uint32_t b1) {
    asm volatile(
        "mma.sync.aligned.m16n8k16.row.col.f32.f16.f16.f32 "
        "{%0,%1,%2,%3}, {%4,%5,%6,%7}, {%8,%9}, {%0,%1,%2,%3};"
        : "+f"(d[0]), "+f"(d[1]), "+f"(d[2]), "+f"(d[3])
        : "r"(a0), "r"(a1), "r"(a2), "r"(a3), "r"(b0), "r"(b1));
}

// ---------------- fast exp (FFMA-only) ----------------
__device__ __forceinline__ float fexp(float x) {
    const float LOG2E = 1.4426950408889634f;
    float t = x * LOG2E;
    float z = t + 12582912.0f;
    int   n = __float_as_int(z) - 0x4B400000;
    float r = z - 12582912.0f;
    float f = t - r;
    float u = f * 0.69314718056f;
    float p = 8.3333333e-3f;
    p = p * u + 4.1666667e-2f;
    p = p * u + 1.6666667e-1f;
    p = p * u + 0.5f;
    p = p * u + 1.0f;
    p = p * u + 1.0f;
    return p * __int_as_float((n + 127) << 23);
}

// ---------------------------------------------------------------------------
// Kernel 0: tf32-round copies (rna) for the proj MMA
// ---------------------------------------------------------------------------
__global__ __launch_bounds__(256) void round_copy(
    const float* __restrict__ src, float* __restrict__ dst, int n4)
{
    int i = blockIdx.x * blockDim.x + threadIdx.x;
    if (i >= n4) return;
    float4 v = ((const float4*)src)[i];
    v.x = tf32r(v.x); v.y = tf32r(v.y); v.z = tf32r(v.z); v.w = tf32r(v.w);
    ((float4*)dst)[i] = v;
}

// ---------------------------------------------------------------------------
// Kernel 1: adjacency -> transposed bitmask  g_adjT[b][j][iw]
// ---------------------------------------------------------------------------
__global__ __launch_bounds__(256) void pack_adjT(const int* __restrict__ adj)
{
    const int b  = blockIdx.z;
    const int iw = blockIdx.y;
    const int j  = blockIdx.x * 256 + threadIdx.x;
    const int* p = adj + ((size_t)b * Nn + (size_t)iw * 32) * Nn + j;
    uint32_t w = 0;
    #pragma unroll
    for (int bit = 0; bit < 32; ++bit)
        w |= (p[(size_t)bit * Nn] != 0 ? 1u : 0u) << bit;
    g_adjT[((size_t)b * Nn + j) * 64 + iw] = w;
}

// ---------------------------------------------------------------------------
// Kernel 2: projection GEMM (mma.sync tf32, cp.async 4-stage) — unchanged R6
// ---------------------------------------------------------------------------
#define PA_OFF 0u
#define PB_OFF 40960u
#define PROJ_SMEM 75776u

__global__ void __launch_bounds__(256, 2) gemm_proj_mma()
{
    extern __shared__ float sm[];
    const uint32_t sb = smem_u32(sm);

    const int t  = threadIdx.x;
    const int m0 = blockIdx.x * 128;
    const int n0 = blockIdx.y * 128;
    const int wid = t >> 5, lane = t & 31;
    const int wm = wid & 1, wn = wid >> 1;
    const int g = lane >> 2, tg = lane & 3;

    float acc[4][4][4];
    #pragma unroll
    for (int i = 0; i < 4; i++)
        #pragma unroll
        for (int j = 0; j < 4; j++)
            #pragma unroll
            for (int r = 0; r < 4; r++) acc[i][j][r] = 0.f;

    const float* asrc[2]; uint32_t adst[2];
    const float* bsrc[2]; uint32_t bdst[2];
    #pragma unroll
    for (int u = 0; u < 2; u++) {
        int gid = u * 256 + t;
        int ar = gid >> 2, ag = gid & 3;
        asrc[u] = g_Fr + (size_t)(m0 + ar) * Dd + ag * 4;
        adst[u] = sb + PA_OFF + (uint32_t)(ar * 80 + ag * 16);
        int br = gid >> 5, bg = gid & 31;
        bsrc[u] = g_Wr + (size_t)br * HC + n0 + bg * 4;
        bdst[u] = sb + PB_OFF + (uint32_t)(br * 544 + bg * 16);
    }

    #pragma unroll
    for (int s = 0; s < 3; s++) {
        #pragma unroll
        for (int u = 0; u < 2; u++) {
            CP_ASYNC16(adst[u] + s * 10240u, asrc[u] + s * 16);
            CP_ASYNC16(bdst[u] + s * 8704u,  bsrc[u] + (size_t)(s * 16) * HC);
        }
        CP_COMMIT();
    }

    for (int kc = 0; kc < 32; ++kc) {
        const int buf = kc & 3;
        CP_WAIT2();
        __syncthreads();
        if (kc < 29) {
            const int s = (kc + 3) & 3, k0 = (kc + 3) * 16;
            #pragma unroll
            for (int u = 0; u < 2; u++) {
                CP_ASYNC16(adst[u] + s * 10240u, asrc[u] + k0);
                CP_ASYNC16(bdst[u] + s * 8704u,  bsrc[u] + (size_t)k0 * HC);
            }
            CP_COMMIT();
        } else {
            CP_COMMIT();
        }

        const uint32_t Ab = sb + PA_OFF + buf * 10240u + (uint32_t)(wm * 64) * 80u;
        const uint32_t Bb = sb + PB_OFF + buf * 8704u + (uint32_t)(wn * 32) * 4u;

        #pragma unroll
        for (int ks = 0; ks < 2; ks++) {
            uint32_t a[4][4];
            #pragma unroll
            for (int mt = 0; mt < 4; mt++) {
                const uint32_t base = Ab + (uint32_t)((mt * 16 + g) * 80 + (ks * 8 + tg) * 4);
                a[mt][0] = lds32u(base);
                a[mt][1] = lds32u(base + 640u);
                a[mt][2] = lds32u(base + 16u);
                a[mt][3] = lds32u(base + 656u);
            }
            uint2 bf[4];
            #pragma unroll
            for (int nt = 0; nt < 4; nt++) {
                const uint32_t base = Bb + (uint32_t)((ks * 8 + tg) * 544 + (nt * 8 + g) * 4);
                bf[nt].x = lds32u(base);
                bf[nt].y = lds32u(base + 2176u);
            }
            #pragma unroll
            for (int mt = 0; mt < 4; mt++)
                #pragma unroll
                for (int nt = 0; nt < 4; nt++)
                    mma8(acc[mt][nt], a[mt][0], a[mt][1], a[mt][2], a[mt][3],
                         bf[nt].x, bf[nt].y);
        }
    }

    #pragma unroll
    for (int mt = 0; mt < 4; mt++) {
        const int m = m0 + wm * 64 + mt * 16 + g;
        #pragma unroll
        for (int nt = 0; nt < 4; nt++) {
            const int n = n0 + wn * 32 + nt * 8 + tg * 2;
            *(float2*)(g_X + (size_t)m * HC + n)       = make_float2(acc[mt][nt][0], acc[mt][nt][1]);
            *(float2*)(g_X + (size_t)(m + 8) * HC + n) = make_float2(acc[mt][nt][2], acc[mt][nt][3]);
        }
    }
}

// ---------------------------------------------------------------------------
// Kernel 3: transpose g_X -> g_XTh [B,HC,N] fp16, i-pair permuted within each
// 32-i chunk so B fragments (m16n8k16) are adjacent ld.shared.v2 pairs:
// element i -> word w=i/2, stored word position p = (w&8)|((w&3)<<1)|((w>>2)&1)
// ---------------------------------------------------------------------------
__global__ __launch_bounds__(256) void xpose() {
    __shared__ float ts[32][33];
    const int b  = blockIdx.z;
    const int n0 = blockIdx.x << 5;
    const int c0 = blockIdx.y << 5;
    const int r  = threadIdx.x >> 5;
    const int cl = threadIdx.x & 31;

    #pragma unroll
    for (int rr = 0; rr < 32; rr += 8)
        ts[r + rr][cl] = g_X[((size_t)b * Nn + n0 + r + rr) * HC + c0 + cl];
    __syncthreads();
    const int w  = cl >> 1, hb = cl & 1;
    const int p  = (w & 8) | ((w & 3) << 1) | ((w >> 2) & 1);
    const int perm = p * 2 + hb;
    #pragma unroll
    for (int rr = 0; rr < 32; rr += 8)
        g_XTh[((size_t)b * HC + c0 + r + rr) * Nn + n0 + perm] =
            __float2half_rn(ts[cl][r + rr]);
}

// ---------------------------------------------------------------------------
// Kernel 4: attention scores -> 4 transposed exp tables [b][h][n].
// Es tables pre-scaled by e^-4 (fp16 range guard; cancels in softmax).
// exp(leaky(s+d)-4) == (Es'*Ed > e^-4) ? Es'*Ed : Es2'*Ed2
// ---------------------------------------------------------------------------
__global__ __launch_bounds__(256) void att_prep(
    const float* __restrict__ att_src, const float* __restrict__ att_dst)
{
    int idx = blockIdx.x * blockDim.x + threadIdx.x;
    if (idx >= Bz * Nn * Hh) return;
    int h  = idx & 7;
    int bn = idx >> 3;
    int b  = bn >> 11;
    int n  = bn & 2047;
    const float* xp = g_X + (size_t)bn * HC + h * Cc;
    const float* ws = att_src + h * Cc;
    const float* wd = att_dst + h * Cc;
    float s = 0.f, d = 0.f;
    #pragma unroll
    for (int c = 0; c < Cc; c += 4) {
        float4 xv = *(const float4*)(xp + c);
        float4 sv = *(const float4*)(ws + c);
        float4 dv = *(const float4*)(wd + c);
        s += xv.x * sv.x + xv.y * sv.y + xv.z * sv.z + xv.w * sv.w;
        d += xv.x * dv.x + xv.y * dv.y + xv.z * dv.z + xv.w * dv.w;
    }
    size_t o = ((size_t)b * Hh + h) * Nn + n;
    g_EsT [o] = fexp(s - 4.0f);
    g_Es2T[o] = fexp(0.2f * s - 4.0f);
    g_EdT [o] = fexp(d);
    g_Ed2T[o] = fexp(0.2f * d);
}

// ---------------------------------------------------------------------------
// Kernel 5: fused masked-softmax aggregation, fp16 m16n8k16 + cp.async x4.
// Block = (b, 2 heads, 128 j); K=2048 sources in 32-i chunks.
// Rows are 64B (32 fp16); 16B-granule XOR swizzle g16 ^= (row>>1)&3 gives
// uniform 2-way bank-pair spread (optimal 2-phase LDS.64).
// ---------------------------------------------------------------------------
#define XT_OFFB  0u        // 4 stages x 8192B (128 rows x 64B)
#define AF_OFFB  32768u    // A frags: 2 heads x 128 rows x 64B = 16384B
#define ADJ_OFFB 49152u    // 4 x 512B
#define ES_OFFB  51200u    // 4 x 512B ([var2][hh2][32 floats])
#define LS_FIDX  13312     // float idx of LS (byte 53248)
#define AGG_SMEM 54272u

__global__ void __launch_bounds__(256, 2) gat_agg_mma(
    const float* __restrict__ bias, float* __restrict__ out)
{
    extern __shared__ float sm[];
    const uint32_t sb = smem_u32(sm);

    const int t  = threadIdx.x;
    const int b  = blockIdx.z;
    const int h0 = blockIdx.y * 2;
    const int j0 = blockIdx.x * 128;

    // producer identity: one (j, head) per thread
    const int pj = t & 127, phead = t >> 7;
    // consumer identity
    const int wid = t >> 5, lane = t & 31;
    const int chead = wid >> 2, ctw = wid & 3;
    const int g = lane >> 2, tg = lane & 3;

    const size_t bn0 = (size_t)b * Nn;
    const float ed  = g_EdT [((size_t)b * Hh + h0 + phead) * Nn + j0 + pj];
    const float ed2 = g_Ed2T[((size_t)b * Hh + h0 + phead) * Nn + j0 + pj];
    const int diag = j0 + pj;
    const int diag_ch = diag >> 5;
    const uint32_t diag_bit = 1u << (diag & 31);

    float acc[2][8][4];
    #pragma unroll
    for (int m = 0; m < 2; m++)
        #pragma unroll
        for (int n = 0; n < 8; n++)
            #pragma unroll
            for (int r = 0; r < 4; r++) acc[m][n][r] = 0.f;

    // cp.async bases: XT fp16 (2 x 16B per thread), adj, Es
    const __half* xsrc[2]; uint32_t xdst[2];
    #pragma unroll
    for (int u = 0; u < 2; u++) {
        int gid = u * 256 + t;
        int row = gid >> 2, q = gid & 3;
        int hh = row >> 6, c = row & 63;
        xsrc[u] = g_XTh + ((size_t)b * HC + (size_t)(h0 + hh) * Cc + c) * Nn + q * 8;
        xdst[u] = sb + XT_OFFB + (uint32_t)(row * 64 + ((q ^ ((row >> 1) & 3)) << 4));
    }
    const uint32_t* ajsrc = g_adjT + (bn0 + j0 + (t & 127)) * 64;
    const float* essrc = nullptr; uint32_t esdst = 0;
    if (t >= 128 && t < 160) {
        int seg = (t - 128) >> 3, gi = t & 7;
        int var = seg >> 1, hh = seg & 1;
        const float* tbl = var ? g_Es2T : g_EsT;
        essrc = tbl + ((size_t)b * Hh + h0 + hh) * Nn + gi * 4;
        esdst = sb + ES_OFFB + (uint32_t)(seg * 128 + gi * 16);
    }

    const uint32_t afw = sb + AF_OFFB + (uint32_t)(phead * 8192 + pj * 64);
    const uint32_t sw_p = (uint32_t)((pj >> 1) & 3);

    // prologue: stages 0..2
    #pragma unroll
    for (int s = 0; s < 3; s++) {
        #pragma unroll
        for (int u = 0; u < 2; u++) CP_ASYNC16(xdst[u] + s * 8192u, xsrc[u] + s * 32);
        if (t < 128) CP_ASYNC4(sb + ADJ_OFFB + s * 512u + (t << 2), ajsrc + s);
        if (t >= 128 && t < 160) CP_ASYNC16(esdst + s * 512u, essrc + s * 32);
        CP_COMMIT();
    }

    float lsum = 0.f;

    for (int ch = 0; ch < 64; ++ch) {
        const int buf = ch & 3;
        CP_WAIT2();
        __syncthreads();   // stage ch visible; consume(ch-1) done

        if (ch < 61) {
            const int s = ch + 3, sb4 = s & 3;
            #pragma unroll
            for (int u = 0; u < 2; u++) CP_ASYNC16(xdst[u] + sb4 * 8192u, xsrc[u] + s * 32);
            if (t < 128) CP_ASYNC4(sb + ADJ_OFFB + sb4 * 512u + (t << 2), ajsrc + s);
            if (t >= 128 && t < 160) CP_ASYNC16(esdst + sb4 * 512u, essrc + s * 32);
            CP_COMMIT();
        } else {
            CP_COMMIT();
        }

        // ---- produce A fragments (fp16 e values, permuted word order)
        uint32_t aw = lds32u(sb + ADJ_OFFB + buf * 512u + (uint32_t)(pj << 2));
        if (ch == diag_ch) aw |= diag_bit;
        const uint32_t esb0 = sb + ES_OFFB + buf * 512u + (uint32_t)(phead * 128);
        const uint32_t esb2 = esb0 + 256u;

        #pragma unroll
        for (int q = 0; q < 4; q++) {
            uint32_t pk[4];
            #pragma unroll
            for (int p4 = 0; p4 < 4; p4++) {
                const int p  = q * 4 + p4;
                const int wd = (p & 8) | ((p & 1) << 2) | ((p >> 1) & 3);
                float2 es  = lds64f(esb0 + (uint32_t)(wd * 8));
                float2 es2 = lds64f(esb2 + (uint32_t)(wd * 8));
                const int i0 = wd * 2;
                float ma0 = es.x * ed;
                float e0 = (ma0 > THRESH) ? ma0 : es2.x * ed2;
                e0 = ((aw >> i0) & 1u) ? e0 : 0.f;
                float ma1 = es.y * ed;
                float e1 = (ma1 > THRESH) ? ma1 : es2.y * ed2;
                e1 = ((aw >> (i0 + 1)) & 1u) ? e1 : 0.f;
                lsum += e0 + e1;
                __half2 h = __floats2half2_rn(e0, e1);
                pk[p4] = *(uint32_t*)&h;
            }
            sts128u(afw + ((q ^ sw_p) << 4), pk[0], pk[1], pk[2], pk[3]);
        }
        __syncthreads();   // A frags visible

        // ---- consume: 32 fp16 MMA per warp
        const uint32_t xtb = sb + XT_OFFB + buf * 8192u + (uint32_t)(chead * 4096);
        const uint32_t afb = sb + AF_OFFB + (uint32_t)(chead * 8192);
        #pragma unroll
        for (int ks = 0; ks < 2; ks++) {
            uint2 ub[8];
            #pragma unroll
            for (int nt = 0; nt < 8; nt++) {
                const int r = nt * 8 + g;
                const uint32_t g16 = (uint32_t)(ks * 2 + (tg >> 1)) ^ (uint32_t)((r >> 1) & 3);
                ub[nt] = lds64u(xtb + (uint32_t)(r * 64) + g16 * 16u + (uint32_t)((tg & 1) * 8));
            }
            #pragma unroll
            for (int mt = 0; mt < 2; mt++) {
                const int R = ctw * 32 + mt * 16 + g;
                const uint32_t g16 = (uint32_t)(ks * 2 + (tg >> 1)) ^ (uint32_t)((R >> 1) & 3);
                const uint32_t byte0 = (uint32_t)(R * 64) + g16 * 16u + (uint32_t)((tg & 1) * 8);
                uint2 rlo = lds64u(afb + byte0);          // row R:   (a0, a2)
                uint2 rhi = lds64u(afb + byte0 + 512u);   // row R+8: (a1, a3) same swizzle
                #pragma unroll
                for (int nt = 0; nt < 8; nt++)
                    mma16(acc[mt][nt], rlo.x, rhi.x, rlo.y, rhi.y,
                          ub[nt].x, ub[nt].y);
            }
        }
    }

    // ---- softmax denominators
    sm[LS_FIDX + phead * 128 + pj] = lsum;
    __syncthreads();

    // ---- epilogue: normalize, +bias, ELU, store
    const float* bp = bias + (size_t)(h0 + chead) * Cc;
    #pragma unroll
    for (int mt = 0; mt < 2; mt++) {
        const int r0 = ctw * 32 + mt * 16 + g;
        const int r1 = r0 + 8;
        const float inv0 = 1.f / sm[LS_FIDX + chead * 128 + r0];
        const float inv1 = 1.f / sm[LS_FIDX + chead * 128 + r1];
        float* o0 = out + (bn0 + j0 + r0) * HC + (size_t)(h0 + chead) * Cc;
        float* o1 = out + (bn0 + j0 + r1) * HC + (size_t)(h0 + chead) * Cc;
        #pragma unroll
        for (int nt = 0; nt < 8; nt++) {
            const int c = nt * 8 + tg * 2;
            const float b0v = bp[c], b1v = bp[c + 1];
            float v0 = acc[mt][nt][0] * inv0 + b0v;
            float v1 = acc[mt][nt][1] * inv0 + b1v;
            float v2 = acc[mt][nt][2] * inv1 + b0v;
            float v3 = acc[mt][nt][3] * inv1 + b1v;
            v0 = v0 > 0.f ? v0 : (fexp(v0) - 1.f);
            v1 = v1 > 0.f ? v1 : (fexp(v1) - 1.f);
            v2 = v2 > 0.f ? v2 : (fexp(v2) - 1.f);
            v3 = v3 > 0.f ? v3 : (fexp(v3) - 1.f);
            *(float2*)(o0 + c) = make_float2(v0, v1);
            *(float2*)(o1 + c) = make_float2(v2, v3);
        }
    }
}

// ---------------------------------------------------------------------------
extern "C" void kernel_launch(void* const* d_in, const int* in_sizes, int n_in,
                              void* d_out, int out_size)
{
    const float* feats   = (const float*)d_in[0];
    const int*   adj     = (const int*)  d_in[1];
    const float* W       = (const float*)d_in[2];
    const float* att_src = (const float*)d_in[3];
    const float* att_dst = (const float*)d_in[4];
    const float* bias    = (const float*)d_in[5];
    float*       out     = (float*)d_out;
    (void)in_sizes; (void)n_in; (void)out_size;

    static bool attr_set = false;
    if (!attr_set) {
        cudaFuncSetAttribute(gat_agg_mma,
                             cudaFuncAttributeMaxDynamicSharedMemorySize, AGG_SMEM);
        cudaFuncSetAttribute(gemm_proj_mma,
                             cudaFuncAttributeMaxDynamicSharedMemorySize, PROJ_SMEM);
        attr_set = true;
    }

    float *dFr, *dWr;
    cudaGetSymbolAddress((void**)&dFr, g_Fr);
    cudaGetSymbolAddress((void**)&dWr, g_Wr);

    round_copy<<<(Bz * Nn * Dd / 4 + 255) / 256, 256>>>(feats, dFr, Bz * Nn * Dd / 4);
    round_copy<<<(Dd * HC / 4 + 255) / 256, 256>>>(W, dWr, Dd * HC / 4);
    pack_adjT<<<dim3(Nn / 256, 64, Bz), 256>>>(adj);
    gemm_proj_mma<<<dim3((Bz * Nn) / 128, HC / 128), 256, PROJ_SMEM>>>();
    xpose<<<dim3(Nn / 32, HC / 32, Bz), 256>>>();
    att_prep<<<(Bz * Nn * Hh + 255) / 256, 256>>>(att_src, att_dst);
    gat_agg_mma<<<dim3(Nn / 128, Hh / 2, Bz), 256, AGG_SMEM>>>(bias, out);
}

// round 8
// speedup vs baseline: 3.8447x; 1.0388x over previous
#include <cuda_runtime.h>
#include <cuda_fp16.h>
#include <cstdint>
#include <math.h>

#define Bz 4
#define Nn 2048
#define Dd 512
#define Hh 8
#define Cc 64
#define HC 512

#define THRESH 0.0183156393f   // e^-4: branch threshold for scaled Es tables

// ---------------- device scratch ----------------
__device__ float  g_X [(size_t)Bz * Nn * HC];    // projected features [B,N,HC]
__device__ __half g_XTh[(size_t)Bz * HC * Nn];   // transposed fp16, i-pair permuted
__device__ float  g_EsT [(size_t)Bz * Hh * Nn];  // exp(s-4)  [b][h][n]
__device__ float  g_Es2T[(size_t)Bz * Hh * Nn];  // exp(.2s-4)
__device__ float  g_EdT [(size_t)Bz * Hh * Nn];  // exp(d)
__device__ float  g_Ed2T[(size_t)Bz * Hh * Nn];  // exp(.2d)
__device__ uint32_t g_adjT[(size_t)Bz * Nn * 64]; // adjacency bits: [b][j][i/32]

// ---------------- helpers ----------------
__device__ __forceinline__ uint32_t smem_u32(const void* p) {
    uint32_t a;
    asm("{ .reg .u64 t; cvta.to.shared.u64 t, %1; cvt.u32.u64 %0, t; }"
        : "=r"(a) : "l"(p));
    return a;
}
__device__ __forceinline__ float tf32r(float x) {
    uint32_t r;
    asm("cvt.rna.tf32.f32 %0, %1;" : "=r"(r) : "f"(x));
    return __uint_as_float(r);
}
__device__ __forceinline__ uint32_t tf32u(uint32_t x) {
    uint32_t r;
    asm("cvt.rna.tf32.f32 %0, %1;" : "=r"(r) : "f"(__uint_as_float(x)));
    return r;
}
__device__ __forceinline__ uint2 lds64u(uint32_t a) {
    uint2 v;
    asm volatile("ld.shared.v2.u32 {%0,%1}, [%2];"
                 : "=r"(v.x), "=r"(v.y) : "r"(a));
    return v;
}
__device__ __forceinline__ float2 lds64f(uint32_t a) {
    float2 v;
    asm volatile("ld.shared.v2.f32 {%0,%1}, [%2];"
                 : "=f"(v.x), "=f"(v.y) : "r"(a));
    return v;
}
__device__ __forceinline__ uint32_t lds32u(uint32_t a) {
    uint32_t v;
    asm volatile("ld.shared.u32 %0, [%1];" : "=r"(v) : "r"(a));
    return v;
}
__device__ __forceinline__ void sts128u(uint32_t a, uint32_t v0, uint32_t v1,
                                        uint32_t v2, uint32_t v3) {
    asm volatile("st.shared.v4.u32 [%0], {%1,%2,%3,%4};"
                 :: "r"(a), "r"(v0), "r"(v1), "r"(v2), "r"(v3) : "memory");
}

#define CP_ASYNC16(dst, src) \
    asm volatile("cp.async.cg.shared.global [%0], [%1], 16;" \
                 :: "r"(dst), "l"(src) : "memory")
#define CP_ASYNC4(dst, src) \
    asm volatile("cp.async.ca.shared.global [%0], [%1], 4;" \
                 :: "r"(dst), "l"(src) : "memory")
#define CP_COMMIT()  asm volatile("cp.async.commit_group;" ::: "memory")
#define CP_WAIT2()   asm volatile("cp.async.wait_group 2;" ::: "memory")

// tf32 mma (proj kernel)
__device__ __forceinline__ void mma8(float* d,
                                     uint32_t a0, uint32_t a1, uint32_t a2, uint32_t a3,
                                     uint32_t b0, uint32_t b1) {
    asm volatile(
        "mma.sync.aligned.m16n8k8.row.col.f32.tf32.tf32.f32 "
        "{%0,%1,%2,%3}, {%4,%5,%6,%7}, {%8,%9}, {%0,%1,%2,%3};"
        : "+f"(d[0]), "+f"(d[1]), "+f"(d[2]), "+f"(d[3])
        : "r"(a0), "r"(a1), "r"(a2), "r"(a3), "r"(b0), "r"(b1));
}
// fp16 mma (agg kernel)
__device__ __forceinline__ void mma16(float* d,
                                      uint32_t a0, uint32_t a1, uint32_t a2, uint32_t a3,
                                      uint32_t b0, uint32_t b1) {
    asm volatile(
        "mma.sync.aligned.m16n8k16.row.col.f32.f16.f16.f32 "
        "{%0,%1,%2,%3}, {%4,%5,%6,%7}, {%8,%9}, {%0,%1,%2,%3};"
        : "+f"(d[0]), "+f"(d[1]), "+f"(d[2]), "+f"(d[3])
        : "r"(a0), "r"(a1), "r"(a2), "r"(a3), "r"(b0), "r"(b1));
}

// ---------------- fast exp (FFMA-only) ----------------
__device__ __forceinline__ float fexp(float x) {
    const float LOG2E = 1.4426950408889634f;
    float t = x * LOG2E;
    float z = t + 12582912.0f;
    int   n = __float_as_int(z) - 0x4B400000;
    float r = z - 12582912.0f;
    float f = t - r;
    float u = f * 0.69314718056f;
    float p = 8.3333333e-3f;
    p = p * u + 4.1666667e-2f;
    p = p * u + 1.6666667e-1f;
    p = p * u + 0.5f;
    p = p * u + 1.0f;
    p = p * u + 1.0f;
    return p * __int_as_float((n + 127) << 23);
}

// ---------------------------------------------------------------------------
// Kernel 1: adjacency -> transposed bitmask  g_adjT[b][j][iw]
// ---------------------------------------------------------------------------
__global__ __launch_bounds__(256) void pack_adjT(const int* __restrict__ adj)
{
    const int b  = blockIdx.z;
    const int iw = blockIdx.y;
    const int j  = blockIdx.x * 256 + threadIdx.x;
    const int* p = adj + ((size_t)b * Nn + (size_t)iw * 32) * Nn + j;
    uint32_t w = 0;
    #pragma unroll
    for (int bit = 0; bit < 32; ++bit)
        w |= (p[(size_t)bit * Nn] != 0 ? 1u : 0u) << bit;
    g_adjT[((size_t)b * Nn + j) * 64 + iw] = w;
}

// ---------------------------------------------------------------------------
// Kernel 2: projection GEMM (mma.sync tf32, cp.async 4-stage).
// Raw fp32 inputs; cvt.rna.tf32 applied in-register after LDS (ALU is idle).
// ---------------------------------------------------------------------------
#define PA_OFF 0u
#define PB_OFF 40960u
#define PROJ_SMEM 75776u

__global__ void __launch_bounds__(256, 2) gemm_proj_mma(
    const float* __restrict__ A, const float* __restrict__ Wm)
{
    extern __shared__ float sm[];
    const uint32_t sb = smem_u32(sm);

    const int t  = threadIdx.x;
    const int m0 = blockIdx.x * 128;
    const int n0 = blockIdx.y * 128;
    const int wid = t >> 5, lane = t & 31;
    const int wm = wid & 1, wn = wid >> 1;
    const int g = lane >> 2, tg = lane & 3;

    float acc[4][4][4];
    #pragma unroll
    for (int i = 0; i < 4; i++)
        #pragma unroll
        for (int j = 0; j < 4; j++)
            #pragma unroll
            for (int r = 0; r < 4; r++) acc[i][j][r] = 0.f;

    const float* asrc[2]; uint32_t adst[2];
    const float* bsrc[2]; uint32_t bdst[2];
    #pragma unroll
    for (int u = 0; u < 2; u++) {
        int gid = u * 256 + t;
        int ar = gid >> 2, ag = gid & 3;
        asrc[u] = A + (size_t)(m0 + ar) * Dd + ag * 4;
        adst[u] = sb + PA_OFF + (uint32_t)(ar * 80 + ag * 16);
        int br = gid >> 5, bg = gid & 31;
        bsrc[u] = Wm + (size_t)br * HC + n0 + bg * 4;
        bdst[u] = sb + PB_OFF + (uint32_t)(br * 544 + bg * 16);
    }

    #pragma unroll
    for (int s = 0; s < 3; s++) {
        #pragma unroll
        for (int u = 0; u < 2; u++) {
            CP_ASYNC16(adst[u] + s * 10240u, asrc[u] + s * 16);
            CP_ASYNC16(bdst[u] + s * 8704u,  bsrc[u] + (size_t)(s * 16) * HC);
        }
        CP_COMMIT();
    }

    for (int kc = 0; kc < 32; ++kc) {
        const int buf = kc & 3;
        CP_WAIT2();
        __syncthreads();
        if (kc < 29) {
            const int s = (kc + 3) & 3, k0 = (kc + 3) * 16;
            #pragma unroll
            for (int u = 0; u < 2; u++) {
                CP_ASYNC16(adst[u] + s * 10240u, asrc[u] + k0);
                CP_ASYNC16(bdst[u] + s * 8704u,  bsrc[u] + (size_t)k0 * HC);
            }
            CP_COMMIT();
        } else {
            CP_COMMIT();
        }

        const uint32_t Ab = sb + PA_OFF + buf * 10240u + (uint32_t)(wm * 64) * 80u;
        const uint32_t Bb = sb + PB_OFF + buf * 8704u + (uint32_t)(wn * 32) * 4u;

        #pragma unroll
        for (int ks = 0; ks < 2; ks++) {
            uint32_t a[4][4];
            #pragma unroll
            for (int mt = 0; mt < 4; mt++) {
                const uint32_t base = Ab + (uint32_t)((mt * 16 + g) * 80 + (ks * 8 + tg) * 4);
                a[mt][0] = tf32u(lds32u(base));
                a[mt][1] = tf32u(lds32u(base + 640u));
                a[mt][2] = tf32u(lds32u(base + 16u));
                a[mt][3] = tf32u(lds32u(base + 656u));
            }
            uint2 bf[4];
            #pragma unroll
            for (int nt = 0; nt < 4; nt++) {
                const uint32_t base = Bb + (uint32_t)((ks * 8 + tg) * 544 + (nt * 8 + g) * 4);
                bf[nt].x = tf32u(lds32u(base));
                bf[nt].y = tf32u(lds32u(base + 2176u));
            }
            #pragma unroll
            for (int mt = 0; mt < 4; mt++)
                #pragma unroll
                for (int nt = 0; nt < 4; nt++)
                    mma8(acc[mt][nt], a[mt][0], a[mt][1], a[mt][2], a[mt][3],
                         bf[nt].x, bf[nt].y);
        }
    }

    #pragma unroll
    for (int mt = 0; mt < 4; mt++) {
        const int m = m0 + wm * 64 + mt * 16 + g;
        #pragma unroll
        for (int nt = 0; nt < 4; nt++) {
            const int n = n0 + wn * 32 + nt * 8 + tg * 2;
            *(float2*)(g_X + (size_t)m * HC + n)       = make_float2(acc[mt][nt][0], acc[mt][nt][1]);
            *(float2*)(g_X + (size_t)(m + 8) * HC + n) = make_float2(acc[mt][nt][2], acc[mt][nt][3]);
        }
    }
}

// ---------------------------------------------------------------------------
// Kernel 3: transpose g_X -> g_XTh [B,HC,N] fp16, i-pair permuted
// ---------------------------------------------------------------------------
__global__ __launch_bounds__(256) void xpose() {
    __shared__ float ts[32][33];
    const int b  = blockIdx.z;
    const int n0 = blockIdx.x << 5;
    const int c0 = blockIdx.y << 5;
    const int r  = threadIdx.x >> 5;
    const int cl = threadIdx.x & 31;

    #pragma unroll
    for (int rr = 0; rr < 32; rr += 8)
        ts[r + rr][cl] = g_X[((size_t)b * Nn + n0 + r + rr) * HC + c0 + cl];
    __syncthreads();
    const int w  = cl >> 1, hb = cl & 1;
    const int p  = (w & 8) | ((w & 3) << 1) | ((w >> 2) & 1);
    const int perm = p * 2 + hb;
    #pragma unroll
    for (int rr = 0; rr < 32; rr += 8)
        g_XTh[((size_t)b * HC + c0 + r + rr) * Nn + n0 + perm] =
            __float2half_rn(ts[cl][r + rr]);
}

// ---------------------------------------------------------------------------
// Kernel 4: attention scores -> 4 transposed exp tables [b][h][n].
// ---------------------------------------------------------------------------
__global__ __launch_bounds__(256) void att_prep(
    const float* __restrict__ att_src, const float* __restrict__ att_dst)
{
    int idx = blockIdx.x * blockDim.x + threadIdx.x;
    if (idx >= Bz * Nn * Hh) return;
    int h  = idx & 7;
    int bn = idx >> 3;
    int b  = bn >> 11;
    int n  = bn & 2047;
    const float* xp = g_X + (size_t)bn * HC + h * Cc;
    const float* ws = att_src + h * Cc;
    const float* wd = att_dst + h * Cc;
    float s = 0.f, d = 0.f;
    #pragma unroll
    for (int c = 0; c < Cc; c += 4) {
        float4 xv = *(const float4*)(xp + c);
        float4 sv = *(const float4*)(ws + c);
        float4 dv = *(const float4*)(wd + c);
        s += xv.x * sv.x + xv.y * sv.y + xv.z * sv.z + xv.w * sv.w;
        d += xv.x * dv.x + xv.y * dv.y + xv.z * dv.z + xv.w * dv.w;
    }
    size_t o = ((size_t)b * Hh + h) * Nn + n;
    g_EsT [o] = fexp(s - 4.0f);
    g_Es2T[o] = fexp(0.2f * s - 4.0f);
    g_EdT [o] = fexp(d);
    g_Ed2T[o] = fexp(0.2f * d);
}

// ---------------------------------------------------------------------------
// Kernel 5: fused masked-softmax aggregation, fp16 MMA, single-barrier
// software pipeline: iteration ch does produce(ch) then consume(ch-1).
// XT 5-stage (prefetch ch+3 never collides with consume ch-1), A-frags
// double-buffered, adj/ES 4-stage.
// ---------------------------------------------------------------------------
#define XT_OFFB  0u        // 5 stages x 8192B
#define AF_OFFB  40960u    // 2 bufs x (2 heads x 128 rows x 64B) = 32768B
#define ADJ_OFFB 73728u    // 4 x 512B
#define ES_OFFB  75776u    // 4 x 512B
#define LS_FIDX  19456     // float idx (byte 77824)
#define AGG_SMEM 78848u

__global__ void __launch_bounds__(256, 2) gat_agg_mma(
    const float* __restrict__ bias, float* __restrict__ out)
{
    extern __shared__ float sm[];
    const uint32_t sb = smem_u32(sm);

    const int t  = threadIdx.x;
    const int b  = blockIdx.z;
    const int h0 = blockIdx.y * 2;
    const int j0 = blockIdx.x * 128;

    // producer identity
    const int pj = t & 127, phead = t >> 7;
    // consumer identity
    const int wid = t >> 5, lane = t & 31;
    const int chead = wid >> 2, ctw = wid & 3;
    const int g = lane >> 2, tg = lane & 3;

    const size_t bn0 = (size_t)b * Nn;
    const float ed  = g_EdT [((size_t)b * Hh + h0 + phead) * Nn + j0 + pj];
    const float ed2 = g_Ed2T[((size_t)b * Hh + h0 + phead) * Nn + j0 + pj];
    const int diag = j0 + pj;
    const int diag_ch = diag >> 5;
    const uint32_t diag_bit = 1u << (diag & 31);

    float acc[2][8][4];
    #pragma unroll
    for (int m = 0; m < 2; m++)
        #pragma unroll
        for (int n = 0; n < 8; n++)
            #pragma unroll
            for (int r = 0; r < 4; r++) acc[m][n][r] = 0.f;

    // cp.async bases
    const __half* xsrc[2]; uint32_t xdst[2];
    #pragma unroll
    for (int u = 0; u < 2; u++) {
        int gid = u * 256 + t;
        int row = gid >> 2, q = gid & 3;
        int hh = row >> 6, c = row & 63;
        xsrc[u] = g_XTh + ((size_t)b * HC + (size_t)(h0 + hh) * Cc + c) * Nn + q * 8;
        xdst[u] = sb + XT_OFFB + (uint32_t)(row * 64 + ((q ^ ((row >> 1) & 3)) << 4));
    }
    const uint32_t* ajsrc = g_adjT + (bn0 + j0 + (t & 127)) * 64;
    const float* essrc = nullptr; uint32_t esdst = 0;
    if (t >= 128 && t < 160) {
        int seg = (t - 128) >> 3, gi = t & 7;
        int var = seg >> 1, hh = seg & 1;
        const float* tbl = var ? g_Es2T : g_EsT;
        essrc = tbl + ((size_t)b * Hh + h0 + hh) * Nn + gi * 4;
        esdst = sb + ES_OFFB + (uint32_t)(seg * 128 + gi * 16);
    }

    const uint32_t afw = sb + AF_OFFB + (uint32_t)(phead * 8192 + pj * 64);
    const uint32_t sw_p = (uint32_t)((pj >> 1) & 3);

    // prologue: stages 0..2 (XT bufs 0..2)
    #pragma unroll
    for (int s = 0; s < 3; s++) {
        #pragma unroll
        for (int u = 0; u < 2; u++) CP_ASYNC16(xdst[u] + s * 8192u, xsrc[u] + s * 32);
        if (t < 128) CP_ASYNC4(sb + ADJ_OFFB + s * 512u + (t << 2), ajsrc + s);
        if (t >= 128 && t < 160) CP_ASYNC16(esdst + s * 512u, essrc + s * 32);
        CP_COMMIT();
    }

    float lsum = 0.f;
    int x5w = 3;   // XT write buf for next issued stage
    int x5r = 0;   // XT read buf for consume(ch-1)

    for (int ch = 0; ch <= 64; ++ch) {
        CP_WAIT2();
        __syncthreads();   // stage ch ready; A-frags(ch-1) visible; consume(ch-2) done

        if (ch < 64) {
            if (ch <= 60) {
                const int s = ch + 3, s4 = s & 3;
                #pragma unroll
                for (int u = 0; u < 2; u++)
                    CP_ASYNC16(xdst[u] + (uint32_t)x5w * 8192u, xsrc[u] + s * 32);
                if (t < 128) CP_ASYNC4(sb + ADJ_OFFB + s4 * 512u + (t << 2), ajsrc + s);
                if (t >= 128 && t < 160) CP_ASYNC16(esdst + s4 * 512u, essrc + s * 32);
                CP_COMMIT();
                x5w = (x5w == 4) ? 0 : x5w + 1;
            } else {
                CP_COMMIT();
            }

            // ---- produce A(ch) into buf ch&1
            const int b4 = ch & 3;
            uint32_t aw = lds32u(sb + ADJ_OFFB + (uint32_t)(b4 * 512) + (uint32_t)(pj << 2));
            if (ch == diag_ch) aw |= diag_bit;
            const uint32_t esb0 = sb + ES_OFFB + (uint32_t)(b4 * 512 + phead * 128);
            const uint32_t esb2 = esb0 + 256u;
            const uint32_t afbase = afw + (uint32_t)((ch & 1) * 16384);

            #pragma unroll
            for (int q = 0; q < 4; q++) {
                uint32_t pk[4];
                #pragma unroll
                for (int p4 = 0; p4 < 4; p4++) {
                    const int p  = q * 4 + p4;
                    const int wd = (p & 8) | ((p & 1) << 2) | ((p >> 1) & 3);
                    float2 es  = lds64f(esb0 + (uint32_t)(wd * 8));
                    float2 es2 = lds64f(esb2 + (uint32_t)(wd * 8));
                    const int i0 = wd * 2;
                    float ma0 = es.x * ed;
                    float e0 = (ma0 > THRESH) ? ma0 : es2.x * ed2;
                    e0 = ((aw >> i0) & 1u) ? e0 : 0.f;
                    float ma1 = es.y * ed;
                    float e1 = (ma1 > THRESH) ? ma1 : es2.y * ed2;
                    e1 = ((aw >> (i0 + 1)) & 1u) ? e1 : 0.f;
                    lsum += e0 + e1;
                    __half2 h = __floats2half2_rn(e0, e1);
                    pk[p4] = *(uint32_t*)&h;
                }
                sts128u(afbase + ((q ^ sw_p) << 4), pk[0], pk[1], pk[2], pk[3]);
            }
        } else {
            CP_COMMIT();
        }

        // ---- consume(ch-1): overlaps with produce(ch) in the same issue stream
        if (ch > 0) {
            const int cc = ch - 1;
            const uint32_t xtb = sb + XT_OFFB + (uint32_t)x5r * 8192u + (uint32_t)(chead * 4096);
            const uint32_t afb = sb + AF_OFFB + (uint32_t)((cc & 1) * 16384 + chead * 8192);
            #pragma unroll
            for (int ks = 0; ks < 2; ks++) {
                uint2 ub[8];
                #pragma unroll
                for (int nt = 0; nt < 8; nt++) {
                    const int r = nt * 8 + g;
                    const uint32_t g16 = (uint32_t)(ks * 2 + (tg >> 1)) ^ (uint32_t)((r >> 1) & 3);
                    ub[nt] = lds64u(xtb + (uint32_t)(r * 64) + g16 * 16u + (uint32_t)((tg & 1) * 8));
                }
                #pragma unroll
                for (int mt = 0; mt < 2; mt++) {
                    const int R = ctw * 32 + mt * 16 + g;
                    const uint32_t g16 = (uint32_t)(ks * 2 + (tg >> 1)) ^ (uint32_t)((R >> 1) & 3);
                    const uint32_t byte0 = (uint32_t)(R * 64) + g16 * 16u + (uint32_t)((tg & 1) * 8);
                    uint2 rlo = lds64u(afb + byte0);
                    uint2 rhi = lds64u(afb + byte0 + 512u);
                    #pragma unroll
                    for (int nt = 0; nt < 8; nt++)
                        mma16(acc[mt][nt], rlo.x, rhi.x, rlo.y, rhi.y,
                              ub[nt].x, ub[nt].y);
                }
            }
            x5r = (x5r == 4) ? 0 : x5r + 1;
        }
    }

    // ---- softmax denominators
    sm[LS_FIDX + phead * 128 + pj] = lsum;
    __syncthreads();

    // ---- epilogue: normalize, +bias, ELU, store
    const float* bp = bias + (size_t)(h0 + chead) * Cc;
    #pragma unroll
    for (int mt = 0; mt < 2; mt++) {
        const int r0 = ctw * 32 + mt * 16 + g;
        const int r1 = r0 + 8;
        const float inv0 = 1.f / sm[LS_FIDX + chead * 128 + r0];
        const float inv1 = 1.f / sm[LS_FIDX + chead * 128 + r1];
        float* o0 = out + (bn0 + j0 + r0) * HC + (size_t)(h0 + chead) * Cc;
        float* o1 = out + (bn0 + j0 + r1) * HC + (size_t)(h0 + chead) * Cc;
        #pragma unroll
        for (int nt = 0; nt < 8; nt++) {
            const int c = nt * 8 + tg * 2;
            const float b0v = bp[c], b1v = bp[c + 1];
            float v0 = acc[mt][nt][0] * inv0 + b0v;
            float v1 = acc[mt][nt][1] * inv0 + b1v;
            float v2 = acc[mt][nt][2] * inv1 + b0v;
            float v3 = acc[mt][nt][3] * inv1 + b1v;
            v0 = v0 > 0.f ? v0 : (fexp(v0) - 1.f);
            v1 = v1 > 0.f ? v1 : (fexp(v1) - 1.f);
            v2 = v2 > 0.f ? v2 : (fexp(v2) - 1.f);
            v3 = v3 > 0.f ? v3 : (fexp(v3) - 1.f);
            *(float2*)(o0 + c) = make_float2(v0, v1);
            *(float2*)(o1 + c) = make_float2(v2, v3);
        }
    }
}

// ---------------------------------------------------------------------------
extern "C" void kernel_launch(void* const* d_in, const int* in_sizes, int n_in,
                              void* d_out, int out_size)
{
    const float* feats   = (const float*)d_in[0];
    const int*   adj     = (const int*)  d_in[1];
    const float* W       = (const float*)d_in[2];
    const float* att_src = (const float*)d_in[3];
    const float* att_dst = (const float*)d_in[4];
    const float* bias    = (const float*)d_in[5];
    float*       out     = (float*)d_out;
    (void)in_sizes; (void)n_in; (void)out_size;

    static bool attr_set = false;
    if (!attr_set) {
        cudaFuncSetAttribute(gat_agg_mma,
                             cudaFuncAttributeMaxDynamicSharedMemorySize, AGG_SMEM);
        cudaFuncSetAttribute(gemm_proj_mma,
                             cudaFuncAttributeMaxDynamicSharedMemorySize, PROJ_SMEM);
        attr_set = true;
    }

    pack_adjT<<<dim3(Nn / 256, 64, Bz), 256>>>(adj);
    gemm_proj_mma<<<dim3((Bz * Nn) / 128, HC / 128), 256, PROJ_SMEM>>>(feats, W);
    xpose<<<dim3(Nn / 32, HC / 32, Bz), 256>>>();
    att_prep<<<(Bz * Nn * Hh + 255) / 256, 256>>>(att_src, att_dst);
    gat_agg_mma<<<dim3(Nn / 128, Hh / 2, Bz), 256, AGG_SMEM>>>(bias, out);
}

// round 9
// speedup vs baseline: 4.3516x; 1.1319x over previous
#include <cuda_runtime.h>
#include <cuda_fp16.h>
#include <cstdint>
#include <math.h>

#define Bz 4
#define Nn 2048
#define Dd 512
#define Hh 8
#define Cc 64
#define HC 512

#define THRESH 0.0183156393f   // e^-4: branch threshold for scaled Es tables
#define ONES_H2 0x3C003C00u    // half2(1.0, 1.0)

// ---------------- device scratch ----------------
__device__ float  g_X [(size_t)Bz * Nn * HC];    // projected features [B,N,HC]
__device__ __half g_XTh[(size_t)Bz * HC * Nn];   // transposed fp16, i-pair permuted
__device__ float  g_EsT [(size_t)Bz * Hh * Nn];  // exp(s-4)  [b][h][n]
__device__ float  g_Es2T[(size_t)Bz * Hh * Nn];  // exp(.2s-4)
__device__ float  g_EdT [(size_t)Bz * Hh * Nn];  // exp(d)
__device__ float  g_Ed2T[(size_t)Bz * Hh * Nn];  // exp(.2d)
__device__ uint32_t g_adjT[(size_t)Bz * Nn * 64]; // adjacency bits: [b][j][i/32]

// ---------------- helpers ----------------
__device__ __forceinline__ uint32_t smem_u32(const void* p) {
    uint32_t a;
    asm("{ .reg .u64 t; cvta.to.shared.u64 t, %1; cvt.u32.u64 %0, t; }"
        : "=r"(a) : "l"(p));
    return a;
}
__device__ __forceinline__ uint32_t tf32u(uint32_t x) {
    uint32_t r;
    asm("cvt.rna.tf32.f32 %0, %1;" : "=r"(r) : "f"(__uint_as_float(x)));
    return r;
}
__device__ __forceinline__ uint2 lds64u(uint32_t a) {
    uint2 v;
    asm volatile("ld.shared.v2.u32 {%0,%1}, [%2];"
                 : "=r"(v.x), "=r"(v.y) : "r"(a));
    return v;
}
__device__ __forceinline__ float2 lds64f(uint32_t a) {
    float2 v;
    asm volatile("ld.shared.v2.f32 {%0,%1}, [%2];"
                 : "=f"(v.x), "=f"(v.y) : "r"(a));
    return v;
}
__device__ __forceinline__ uint32_t lds32u(uint32_t a) {
    uint32_t v;
    asm volatile("ld.shared.u32 %0, [%1];" : "=r"(v) : "r"(a));
    return v;
}

#define CP_ASYNC16(dst, src) \
    asm volatile("cp.async.cg.shared.global [%0], [%1], 16;" \
                 :: "r"(dst), "l"(src) : "memory")
#define CP_ASYNC4(dst, src) \
    asm volatile("cp.async.ca.shared.global [%0], [%1], 4;" \
                 :: "r"(dst), "l"(src) : "memory")
#define CP_COMMIT()  asm volatile("cp.async.commit_group;" ::: "memory")
#define CP_WAIT2()   asm volatile("cp.async.wait_group 2;" ::: "memory")

// tf32 mma (proj kernel)
__device__ __forceinline__ void mma8(float* d,
                                     uint32_t a0, uint32_t a1, uint32_t a2, uint32_t a3,
                                     uint32_t b0, uint32_t b1) {
    asm volatile(
        "mma.sync.aligned.m16n8k8.row.col.f32.tf32.tf32.f32 "
        "{%0,%1,%2,%3}, {%4,%5,%6,%7}, {%8,%9}, {%0,%1,%2,%3};"
        : "+f"(d[0]), "+f"(d[1]), "+f"(d[2]), "+f"(d[3])
        : "r"(a0), "r"(a1), "r"(a2), "r"(a3), "r"(b0), "r"(b1));
}
// fp16 mma (agg kernel)
__device__ __forceinline__ void mma16(float* d,
                                      uint32_t a0, uint32_t a1, uint32_t a2, uint32_t a3,
                                      uint32_t b0, uint32_t b1) {
    asm volatile(
        "mma.sync.aligned.m16n8k16.row.col.f32.f16.f16.f32 "
        "{%0,%1,%2,%3}, {%4,%5,%6,%7}, {%8,%9}, {%0,%1,%2,%3};"
        : "+f"(d[0]), "+f"(d[1]), "+f"(d[2]), "+f"(d[3])
        : "r"(a0), "r"(a1), "r"(a2), "r"(a3), "r"(b0), "r"(b1));
}

// ---------------- fast exp (FFMA-only) ----------------
__device__ __forceinline__ float fexp(float x) {
    const float LOG2E = 1.4426950408889634f;
    float t = x * LOG2E;
    float z = t + 12582912.0f;
    int   n = __float_as_int(z) - 0x4B400000;
    float r = z - 12582912.0f;
    float f = t - r;
    float u = f * 0.69314718056f;
    float p = 8.3333333e-3f;
    p = p * u + 4.1666667e-2f;
    p = p * u + 1.6666667e-1f;
    p = p * u + 0.5f;
    p = p * u + 1.0f;
    p = p * u + 1.0f;
    return p * __int_as_float((n + 127) << 23);
}

// ---------------------------------------------------------------------------
// Kernel 1: adjacency -> transposed bitmask  g_adjT[b][j][iw]
// ---------------------------------------------------------------------------
__global__ __launch_bounds__(256) void pack_adjT(const int* __restrict__ adj)
{
    const int b  = blockIdx.z;
    const int iw = blockIdx.y;
    const int j  = blockIdx.x * 256 + threadIdx.x;
    const int* p = adj + ((size_t)b * Nn + (size_t)iw * 32) * Nn + j;
    uint32_t w = 0;
    #pragma unroll
    for (int bit = 0; bit < 32; ++bit)
        w |= (p[(size_t)bit * Nn] != 0 ? 1u : 0u) << bit;
    g_adjT[((size_t)b * Nn + j) * 64 + iw] = w;
}

// ---------------------------------------------------------------------------
// Kernel 2: projection GEMM (mma.sync tf32, cp.async 4-stage) — unchanged
// ---------------------------------------------------------------------------
#define PA_OFF 0u
#define PB_OFF 40960u
#define PROJ_SMEM 75776u

__global__ void __launch_bounds__(256, 2) gemm_proj_mma(
    const float* __restrict__ A, const float* __restrict__ Wm)
{
    extern __shared__ float sm[];
    const uint32_t sb = smem_u32(sm);

    const int t  = threadIdx.x;
    const int m0 = blockIdx.x * 128;
    const int n0 = blockIdx.y * 128;
    const int wid = t >> 5, lane = t & 31;
    const int wm = wid & 1, wn = wid >> 1;
    const int g = lane >> 2, tg = lane & 3;

    float acc[4][4][4];
    #pragma unroll
    for (int i = 0; i < 4; i++)
        #pragma unroll
        for (int j = 0; j < 4; j++)
            #pragma unroll
            for (int r = 0; r < 4; r++) acc[i][j][r] = 0.f;

    const float* asrc[2]; uint32_t adst[2];
    const float* bsrc[2]; uint32_t bdst[2];
    #pragma unroll
    for (int u = 0; u < 2; u++) {
        int gid = u * 256 + t;
        int ar = gid >> 2, ag = gid & 3;
        asrc[u] = A + (size_t)(m0 + ar) * Dd + ag * 4;
        adst[u] = sb + PA_OFF + (uint32_t)(ar * 80 + ag * 16);
        int br = gid >> 5, bg = gid & 31;
        bsrc[u] = Wm + (size_t)br * HC + n0 + bg * 4;
        bdst[u] = sb + PB_OFF + (uint32_t)(br * 544 + bg * 16);
    }

    #pragma unroll
    for (int s = 0; s < 3; s++) {
        #pragma unroll
        for (int u = 0; u < 2; u++) {
            CP_ASYNC16(adst[u] + s * 10240u, asrc[u] + s * 16);
            CP_ASYNC16(bdst[u] + s * 8704u,  bsrc[u] + (size_t)(s * 16) * HC);
        }
        CP_COMMIT();
    }

    for (int kc = 0; kc < 32; ++kc) {
        const int buf = kc & 3;
        CP_WAIT2();
        __syncthreads();
        if (kc < 29) {
            const int s = (kc + 3) & 3, k0 = (kc + 3) * 16;
            #pragma unroll
            for (int u = 0; u < 2; u++) {
                CP_ASYNC16(adst[u] + s * 10240u, asrc[u] + k0);
                CP_ASYNC16(bdst[u] + s * 8704u,  bsrc[u] + (size_t)k0 * HC);
            }
            CP_COMMIT();
        } else {
            CP_COMMIT();
        }

        const uint32_t Ab = sb + PA_OFF + buf * 10240u + (uint32_t)(wm * 64) * 80u;
        const uint32_t Bb = sb + PB_OFF + buf * 8704u + (uint32_t)(wn * 32) * 4u;

        #pragma unroll
        for (int ks = 0; ks < 2; ks++) {
            uint32_t a[4][4];
            #pragma unroll
            for (int mt = 0; mt < 4; mt++) {
                const uint32_t base = Ab + (uint32_t)((mt * 16 + g) * 80 + (ks * 8 + tg) * 4);
                a[mt][0] = tf32u(lds32u(base));
                a[mt][1] = tf32u(lds32u(base + 640u));
                a[mt][2] = tf32u(lds32u(base + 16u));
                a[mt][3] = tf32u(lds32u(base + 656u));
            }
            uint2 bf[4];
            #pragma unroll
            for (int nt = 0; nt < 4; nt++) {
                const uint32_t base = Bb + (uint32_t)((ks * 8 + tg) * 544 + (nt * 8 + g) * 4);
                bf[nt].x = tf32u(lds32u(base));
                bf[nt].y = tf32u(lds32u(base + 2176u));
            }
            #pragma unroll
            for (int mt = 0; mt < 4; mt++)
                #pragma unroll
                for (int nt = 0; nt < 4; nt++)
                    mma8(acc[mt][nt], a[mt][0], a[mt][1], a[mt][2], a[mt][3],
                         bf[nt].x, bf[nt].y);
        }
    }

    #pragma unroll
    for (int mt = 0; mt < 4; mt++) {
        const int m = m0 + wm * 64 + mt * 16 + g;
        #pragma unroll
        for (int nt = 0; nt < 4; nt++) {
            const int n = n0 + wn * 32 + nt * 8 + tg * 2;
            *(float2*)(g_X + (size_t)m * HC + n)       = make_float2(acc[mt][nt][0], acc[mt][nt][1]);
            *(float2*)(g_X + (size_t)(m + 8) * HC + n) = make_float2(acc[mt][nt][2], acc[mt][nt][3]);
        }
    }
}

// ---------------------------------------------------------------------------
// Kernel 3: transpose g_X -> g_XTh [B,HC,N] fp16, i-pair permuted
// ---------------------------------------------------------------------------
__global__ __launch_bounds__(256) void xpose() {
    __shared__ float ts[32][33];
    const int b  = blockIdx.z;
    const int n0 = blockIdx.x << 5;
    const int c0 = blockIdx.y << 5;
    const int r  = threadIdx.x >> 5;
    const int cl = threadIdx.x & 31;

    #pragma unroll
    for (int rr = 0; rr < 32; rr += 8)
        ts[r + rr][cl] = g_X[((size_t)b * Nn + n0 + r + rr) * HC + c0 + cl];
    __syncthreads();
    const int w  = cl >> 1, hb = cl & 1;
    const int p  = (w & 8) | ((w & 3) << 1) | ((w >> 2) & 1);
    const int perm = p * 2 + hb;
    #pragma unroll
    for (int rr = 0; rr < 32; rr += 8)
        g_XTh[((size_t)b * HC + c0 + r + rr) * Nn + n0 + perm] =
            __float2half_rn(ts[cl][r + rr]);
}

// ---------------------------------------------------------------------------
// Kernel 4: attention scores, warp-per-(b,n): coalesced x loads, att vectors
// staged in SMEM, 16-lane shfl reduction, one table write per lane.
// ---------------------------------------------------------------------------
__global__ __launch_bounds__(256) void att_prep(
    const float* __restrict__ att_src, const float* __restrict__ att_dst)
{
    __shared__ float sa[HC], sdv[HC];
    const int t = threadIdx.x;
    if (t < 128)       ((float4*)sa)[t]        = ((const float4*)att_src)[t];
    else               ((float4*)sdv)[t - 128] = ((const float4*)att_dst)[t - 128];
    __syncthreads();

    const int w = t >> 5, l = t & 31;
    const int bn = blockIdx.x * 8 + w;
    const int b = bn >> 11, n = bn & 2047;
    const float* xp = g_X + (size_t)bn * HC;

    float sp[4], dp[4];
    #pragma unroll
    for (int p = 0; p < 4; p++) {
        const int c = p * 128 + l * 4;
        float4 xv = *(const float4*)(xp + c);
        float4 av = *(const float4*)(sa + c);
        float4 dv = *(const float4*)(sdv + c);
        sp[p] = xv.x * av.x + xv.y * av.y + xv.z * av.z + xv.w * av.w;
        dp[p] = xv.x * dv.x + xv.y * dv.y + xv.z * dv.z + xv.w * dv.w;
    }
    #pragma unroll
    for (int o = 1; o < 16; o <<= 1) {
        #pragma unroll
        for (int p = 0; p < 4; p++) {
            sp[p] += __shfl_xor_sync(0xffffffffu, sp[p], o);
            dp[p] += __shfl_xor_sync(0xffffffffu, dp[p], o);
        }
    }
    const int hi = l >> 4, q = l & 15;
    const int p = q >> 2, v = q & 3;
    const int h = p * 2 + hi;
    const float s = sp[p], d = dp[p];
    const size_t o = ((size_t)b * Hh + h) * Nn + n;
    if      (v == 0) g_EsT [o] = fexp(s - 4.0f);
    else if (v == 1) g_Es2T[o] = fexp(0.2f * s - 4.0f);
    else if (v == 2) g_EdT [o] = fexp(d);
    else             g_Ed2T[o] = fexp(0.2f * d);
}

// ---------------------------------------------------------------------------
// Kernel 5: fused masked-softmax aggregation, fp16 MMA.
// A-fragments built DIRECTLY in consumer registers (no SMEM round trip);
// denominator accumulated via ones-column MMA (exactly matches numerator
// rounding). One barrier per chunk. XT/adj/ES all 4-stage cp.async.
// ---------------------------------------------------------------------------
#define XT_OFFB  0u        // 4 stages x 8192B
#define ADJ_OFFB 32768u    // 4 x 512B
#define ES_OFFB  34816u    // 4 x 512B
#define AGG_SMEM 36864u

__global__ void __launch_bounds__(256, 2) gat_agg_mma(
    const float* __restrict__ bias, float* __restrict__ out)
{
    extern __shared__ float sm[];
    const uint32_t sb = smem_u32(sm);

    const int t  = threadIdx.x;
    const int b  = blockIdx.z;
    const int h0 = blockIdx.y * 2;
    const int j0 = blockIdx.x * 128;

    const int wid = t >> 5, lane = t & 31;
    const int chead = wid >> 2, ctw = wid & 3;
    const int g = lane >> 2, tg = lane & 3;

    const size_t bn0 = (size_t)b * Nn;
    const size_t edb = ((size_t)b * Hh + h0 + chead) * Nn + j0;

    // 4 fragment rows this thread owns: base + {0,8,16,24}
    int rows[4]; float ed[4], ed2[4]; int dch[4]; uint32_t dbit[4];
    #pragma unroll
    for (int r = 0; r < 4; r++) {
        rows[r] = ctw * 32 + (r >> 1) * 16 + (r & 1) * 8 + g;
        ed[r]  = g_EdT [edb + rows[r]];
        ed2[r] = g_Ed2T[edb + rows[r]];
        dch[r]  = (j0 + rows[r]) >> 5;
        dbit[r] = 1u << ((j0 + rows[r]) & 31);
    }

    float acc[2][8][4];
    #pragma unroll
    for (int m = 0; m < 2; m++)
        #pragma unroll
        for (int n = 0; n < 8; n++)
            #pragma unroll
            for (int r = 0; r < 4; r++) acc[m][n][r] = 0.f;
    float accl[2][4];
    #pragma unroll
    for (int m = 0; m < 2; m++)
        #pragma unroll
        for (int r = 0; r < 4; r++) accl[m][r] = 0.f;

    // cp.async bases
    const __half* xsrc[2]; uint32_t xdst[2];
    #pragma unroll
    for (int u = 0; u < 2; u++) {
        int gid = u * 256 + t;
        int row = gid >> 2, q = gid & 3;
        int hh = row >> 6, c = row & 63;
        xsrc[u] = g_XTh + ((size_t)b * HC + (size_t)(h0 + hh) * Cc + c) * Nn + q * 8;
        xdst[u] = sb + XT_OFFB + (uint32_t)(row * 64 + ((q ^ ((row >> 1) & 3)) << 4));
    }
    const uint32_t* ajsrc = g_adjT + (bn0 + j0 + (t & 127)) * 64;
    const float* essrc = nullptr; uint32_t esdst = 0;
    if (t >= 128 && t < 160) {
        int seg = (t - 128) >> 3, gi = t & 7;
        int var = seg >> 1, hh = seg & 1;
        const float* tbl = var ? g_Es2T : g_EsT;
        essrc = tbl + ((size_t)b * Hh + h0 + hh) * Nn + gi * 4;
        esdst = sb + ES_OFFB + (uint32_t)(seg * 128 + gi * 16);
    }

    // prologue: stages 0..2
    #pragma unroll
    for (int s = 0; s < 3; s++) {
        #pragma unroll
        for (int u = 0; u < 2; u++) CP_ASYNC16(xdst[u] + s * 8192u, xsrc[u] + s * 32);
        if (t < 128) CP_ASYNC4(sb + ADJ_OFFB + s * 512u + (t << 2), ajsrc + s);
        if (t >= 128 && t < 160) CP_ASYNC16(esdst + s * 512u, essrc + s * 32);
        CP_COMMIT();
    }

    for (int ch = 0; ch < 64; ++ch) {
        const int s4 = ch & 3;
        CP_WAIT2();
        __syncthreads();   // stage ch ready; all reads of stage ch-1 done

        if (ch <= 60) {
            const int s = ch + 3, sw = s & 3;
            #pragma unroll
            for (int u = 0; u < 2; u++)
                CP_ASYNC16(xdst[u] + (uint32_t)sw * 8192u, xsrc[u] + s * 32);
            if (t < 128) CP_ASYNC4(sb + ADJ_OFFB + (uint32_t)sw * 512u + (t << 2), ajsrc + s);
            if (t >= 128 && t < 160) CP_ASYNC16(esdst + (uint32_t)sw * 512u, essrc + s * 32);
            CP_COMMIT();
        } else {
            CP_COMMIT();
        }

        // adjacency words for my 4 rows (+ self-loop bit)
        uint32_t aw[4];
        #pragma unroll
        for (int r = 0; r < 4; r++) {
            aw[r] = lds32u(sb + ADJ_OFFB + (uint32_t)(s4 * 512) + (uint32_t)(rows[r] << 2));
            if (ch == dch[r]) aw[r] |= dbit[r];
        }

        const uint32_t esb0 = sb + ES_OFFB + (uint32_t)(s4 * 512 + chead * 128);
        const uint32_t esb2 = esb0 + 256u;
        const uint32_t xtb  = sb + XT_OFFB + (uint32_t)(s4 * 8192 + chead * 4096);

        #pragma unroll
        for (int ks = 0; ks < 2; ks++) {
            const int sh = ks * 16 + 2 * tg;
            float2 eA  = lds64f(esb0 + (uint32_t)(sh * 4));
            float2 eB  = lds64f(esb0 + (uint32_t)((sh + 8) * 4));
            float2 e2A = lds64f(esb2 + (uint32_t)(sh * 4));
            float2 e2B = lds64f(esb2 + (uint32_t)((sh + 8) * 4));

            uint32_t aT[4], bT[4];
            #pragma unroll
            for (int r = 0; r < 4; r++) {
                float m0v = eA.x * ed[r];
                float a0 = (m0v > THRESH) ? m0v : e2A.x * ed2[r];
                a0 = ((aw[r] >> sh) & 1u) ? a0 : 0.f;
                float m1v = eA.y * ed[r];
                float a1 = (m1v > THRESH) ? m1v : e2A.y * ed2[r];
                a1 = ((aw[r] >> (sh + 1)) & 1u) ? a1 : 0.f;
                float m2v = eB.x * ed[r];
                float b0 = (m2v > THRESH) ? m2v : e2B.x * ed2[r];
                b0 = ((aw[r] >> (sh + 8)) & 1u) ? b0 : 0.f;
                float m3v = eB.y * ed[r];
                float b1 = (m3v > THRESH) ? m3v : e2B.y * ed2[r];
                b1 = ((aw[r] >> (sh + 9)) & 1u) ? b1 : 0.f;
                __half2 hA = __floats2half2_rn(a0, a1);
                __half2 hB = __floats2half2_rn(b0, b1);
                aT[r] = *(uint32_t*)&hA;
                bT[r] = *(uint32_t*)&hB;
            }

            #pragma unroll
            for (int nt = 0; nt < 8; nt++) {
                const int r = nt * 8 + g;
                const uint32_t g16 = (uint32_t)(ks * 2 + (tg >> 1)) ^ (uint32_t)((r >> 1) & 3);
                uint2 u = lds64u(xtb + (uint32_t)(r * 64) + g16 * 16u + (uint32_t)((tg & 1) * 8));
                mma16(acc[0][nt], aT[0], aT[1], bT[0], bT[1], u.x, u.y);
                mma16(acc[1][nt], aT[2], aT[3], bT[2], bT[3], u.x, u.y);
            }
            // denominator: ones-column mma (same fp16 e as numerator)
            mma16(accl[0], aT[0], aT[1], bT[0], bT[1], ONES_H2, ONES_H2);
            mma16(accl[1], aT[2], aT[3], bT[2], bT[3], ONES_H2, ONES_H2);
        }
    }

    // ---- epilogue: normalize, +bias, ELU, store (denominators in accl)
    const float* bp = bias + (size_t)(h0 + chead) * Cc;
    #pragma unroll
    for (int mt = 0; mt < 2; mt++) {
        const int r0 = ctw * 32 + mt * 16 + g;
        const int r1 = r0 + 8;
        const float inv0 = 1.f / accl[mt][0];
        const float inv1 = 1.f / accl[mt][2];
        float* o0 = out + (bn0 + j0 + r0) * HC + (size_t)(h0 + chead) * Cc;
        float* o1 = out + (bn0 + j0 + r1) * HC + (size_t)(h0 + chead) * Cc;
        #pragma unroll
        for (int nt = 0; nt < 8; nt++) {
            const int c = nt * 8 + tg * 2;
            const float b0v = bp[c], b1v = bp[c + 1];
            float v0 = acc[0][nt][0] * 0.f; // placeholder removed below
            (void)v0;
            float w0 = acc[mt][nt][0] * inv0 + b0v;
            float w1 = acc[mt][nt][1] * inv0 + b1v;
            float w2 = acc[mt][nt][2] * inv1 + b0v;
            float w3 = acc[mt][nt][3] * inv1 + b1v;
            w0 = w0 > 0.f ? w0 : (fexp(w0) - 1.f);
            w1 = w1 > 0.f ? w1 : (fexp(w1) - 1.f);
            w2 = w2 > 0.f ? w2 : (fexp(w2) - 1.f);
            w3 = w3 > 0.f ? w3 : (fexp(w3) - 1.f);
            *(float2*)(o0 + c) = make_float2(w0, w1);
            *(float2*)(o1 + c) = make_float2(w2, w3);
        }
    }
}

// ---------------------------------------------------------------------------
extern "C" void kernel_launch(void* const* d_in, const int* in_sizes, int n_in,
                              void* d_out, int out_size)
{
    const float* feats   = (const float*)d_in[0];
    const int*   adj     = (const int*)  d_in[1];
    const float* W       = (const float*)d_in[2];
    const float* att_src = (const float*)d_in[3];
    const float* att_dst = (const float*)d_in[4];
    const float* bias    = (const float*)d_in[5];
    float*       out     = (float*)d_out;
    (void)in_sizes; (void)n_in; (void)out_size;

    static bool attr_set = false;
    if (!attr_set) {
        cudaFuncSetAttribute(gat_agg_mma,
                             cudaFuncAttributeMaxDynamicSharedMemorySize, AGG_SMEM);
        cudaFuncSetAttribute(gemm_proj_mma,
                             cudaFuncAttributeMaxDynamicSharedMemorySize, PROJ_SMEM);
        attr_set = true;
    }

    pack_adjT<<<dim3(Nn / 256, 64, Bz), 256>>>(adj);
    gemm_proj_mma<<<dim3((Bz * Nn) / 128, HC / 128), 256, PROJ_SMEM>>>(feats, W);
    xpose<<<dim3(Nn / 32, HC / 32, Bz), 256>>>();
    att_prep<<<(Bz * Nn) / 8, 256>>>(att_src, att_dst);
    gat_agg_mma<<<dim3(Nn / 128, Hh / 2, Bz), 256, AGG_SMEM>>>(bias, out);
}

// round 10
// speedup vs baseline: 5.0127x; 1.1519x over previous
#include <cuda_runtime.h>
#include <cuda_fp16.h>
#include <cstdint>
#include <math.h>

#define Bz 4
#define Nn 2048
#define Dd 512
#define Hh 8
#define Cc 64
#define HC 512

// ---------------- device scratch ----------------
__device__ float  g_X [(size_t)Bz * Nn * HC];    // projected features [B,N,HC]
__device__ __half g_XTh[(size_t)Bz * HC * Nn];   // transposed fp16, i-pair permuted
__device__ float  g_EsT [(size_t)Bz * Hh * Nn];  // exp(s-4)  [b][h][n]
__device__ float  g_Es2T[(size_t)Bz * Hh * Nn];  // exp(.2s-4)
__device__ float  g_EdT [(size_t)Bz * Hh * Nn];  // exp(d)
__device__ float  g_Ed2T[(size_t)Bz * Hh * Nn];  // exp(.2d)
__device__ unsigned short g_adjH[(size_t)Bz * Nn * Nn]; // mask: [b][j][i] 0xFFFF/0, diag folded

// ---------------- helpers ----------------
__device__ __forceinline__ uint32_t smem_u32(const void* p) {
    uint32_t a;
    asm("{ .reg .u64 t; cvta.to.shared.u64 t, %1; cvt.u32.u64 %0, t; }"
        : "=r"(a) : "l"(p));
    return a;
}
__device__ __forceinline__ uint32_t tf32u(uint32_t x) {
    uint32_t r;
    asm("cvt.rna.tf32.f32 %0, %1;" : "=r"(r) : "f"(__uint_as_float(x)));
    return r;
}
__device__ __forceinline__ uint2 lds64u(uint32_t a) {
    uint2 v;
    asm volatile("ld.shared.v2.u32 {%0,%1}, [%2];"
                 : "=r"(v.x), "=r"(v.y) : "r"(a));
    return v;
}
__device__ __forceinline__ float2 lds64f(uint32_t a) {
    float2 v;
    asm volatile("ld.shared.v2.f32 {%0,%1}, [%2];"
                 : "=f"(v.x), "=f"(v.y) : "r"(a));
    return v;
}
__device__ __forceinline__ uint32_t lds32u(uint32_t a) {
    uint32_t v;
    asm volatile("ld.shared.u32 %0, [%1];" : "=r"(v) : "r"(a));
    return v;
}
__device__ __forceinline__ void sts16(uint32_t a, uint16_t v) {
    asm volatile("st.shared.u16 [%0], %1;" :: "r"(a), "h"(v) : "memory");
}
__device__ __forceinline__ uint16_t f2h(float f) {
    __half h = __float2half_rn(f);
    return *(uint16_t*)&h;
}

#define CP_ASYNC16(dst, src) \
    asm volatile("cp.async.cg.shared.global [%0], [%1], 16;" \
                 :: "r"(dst), "l"(src) : "memory")
#define CP_COMMIT()  asm volatile("cp.async.commit_group;" ::: "memory")
#define CP_WAIT2()   asm volatile("cp.async.wait_group 2;" ::: "memory")

// tf32 mma (proj kernel)
__device__ __forceinline__ void mma8(float* d,
                                     uint32_t a0, uint32_t a1, uint32_t a2, uint32_t a3,
                                     uint32_t b0, uint32_t b1) {
    asm volatile(
        "mma.sync.aligned.m16n8k8.row.col.f32.tf32.tf32.f32 "
        "{%0,%1,%2,%3}, {%4,%5,%6,%7}, {%8,%9}, {%0,%1,%2,%3};"
        : "+f"(d[0]), "+f"(d[1]), "+f"(d[2]), "+f"(d[3])
        : "r"(a0), "r"(a1), "r"(a2), "r"(a3), "r"(b0), "r"(b1));
}
// fp16 mma (agg kernel)
__device__ __forceinline__ void mma16(float* d,
                                      uint32_t a0, uint32_t a1, uint32_t a2, uint32_t a3,
                                      uint32_t b0, uint32_t b1) {
    asm volatile(
        "mma.sync.aligned.m16n8k16.row.col.f32.f16.f16.f32 "
        "{%0,%1,%2,%3}, {%4,%5,%6,%7}, {%8,%9}, {%0,%1,%2,%3};"
        : "+f"(d[0]), "+f"(d[1]), "+f"(d[2]), "+f"(d[3])
        : "r"(a0), "r"(a1), "r"(a2), "r"(a3), "r"(b0), "r"(b1));
}
#define ONES_H2 0x3C003C00u

// ---------------- fast exp (FFMA-only) ----------------
__device__ __forceinline__ float fexp(float x) {
    const float LOG2E = 1.4426950408889634f;
    float t = x * LOG2E;
    float z = t + 12582912.0f;
    int   n = __float_as_int(z) - 0x4B400000;
    float r = z - 12582912.0f;
    float f = t - r;
    float u = f * 0.69314718056f;
    float p = 8.3333333e-3f;
    p = p * u + 4.1666667e-2f;
    p = p * u + 1.6666667e-1f;
    p = p * u + 0.5f;
    p = p * u + 1.0f;
    p = p * u + 1.0f;
    return p * __int_as_float((n + 127) << 23);
}

// ---------------------------------------------------------------------------
// Kernel 1: adjacency -> transposed fp16 AND-mask  g_adjH[b][j][i], diag folded
// ---------------------------------------------------------------------------
__global__ __launch_bounds__(256) void pack_adjH(const int* __restrict__ adj)
{
    __shared__ unsigned short ts[32][36];
    const int b  = blockIdx.z;
    const int i0 = blockIdx.y * 32;
    const int j0 = blockIdx.x * 32;
    const int t  = threadIdx.x;
    const int r  = t >> 3;    // i offset 0..31
    const int c4 = t & 7;     // j group

    // read adj[b][i0+r][j0+c4*4..+3] (coalesced along j)
    int4 v = *(const int4*)(adj + ((size_t)b * Nn + i0 + r) * Nn + j0 + c4 * 4);
    const int ii = i0 + r;
    ts[r][c4 * 4 + 0] = (v.x != 0 || ii == j0 + c4 * 4 + 0) ? 0xFFFFu : 0u;
    ts[r][c4 * 4 + 1] = (v.y != 0 || ii == j0 + c4 * 4 + 1) ? 0xFFFFu : 0u;
    ts[r][c4 * 4 + 2] = (v.z != 0 || ii == j0 + c4 * 4 + 2) ? 0xFFFFu : 0u;
    ts[r][c4 * 4 + 3] = (v.w != 0 || ii == j0 + c4 * 4 + 3) ? 0xFFFFu : 0u;
    __syncthreads();

    // write adjH[b][j0+jr][i0 + ic4*4 ..] (coalesced along i)
    const int jr  = t >> 3;
    const int ic4 = t & 7;
    uint32_t lo = (uint32_t)ts[ic4 * 4 + 0][jr] | ((uint32_t)ts[ic4 * 4 + 1][jr] << 16);
    uint32_t hi = (uint32_t)ts[ic4 * 4 + 2][jr] | ((uint32_t)ts[ic4 * 4 + 3][jr] << 16);
    *(uint2*)(g_adjH + ((size_t)b * Nn + j0 + jr) * Nn + i0 + ic4 * 4) =
        make_uint2(lo, hi);
}

// ---------------------------------------------------------------------------
// Kernel 2: projection GEMM (mma.sync tf32, cp.async 4-stage) + fused
// transposed fp16 epilogue (writes g_X AND g_XTh; xpose kernel eliminated).
// ---------------------------------------------------------------------------
#define PA_OFF 0u
#define PB_OFF 40960u
#define PROJ_SMEM 75776u

__global__ void __launch_bounds__(256, 2) gemm_proj_mma(
    const float* __restrict__ A, const float* __restrict__ Wm)
{
    extern __shared__ float sm[];
    const uint32_t sb = smem_u32(sm);

    const int t  = threadIdx.x;
    const int m0 = blockIdx.x * 128;
    const int n0 = blockIdx.y * 128;
    const int wid = t >> 5, lane = t & 31;
    const int wm = wid & 1, wn = wid >> 1;
    const int g = lane >> 2, tg = lane & 3;

    float acc[4][4][4];
    #pragma unroll
    for (int i = 0; i < 4; i++)
        #pragma unroll
        for (int j = 0; j < 4; j++)
            #pragma unroll
            for (int r = 0; r < 4; r++) acc[i][j][r] = 0.f;

    const float* asrc[2]; uint32_t adst[2];
    const float* bsrc[2]; uint32_t bdst[2];
    #pragma unroll
    for (int u = 0; u < 2; u++) {
        int gid = u * 256 + t;
        int ar = gid >> 2, ag = gid & 3;
        asrc[u] = A + (size_t)(m0 + ar) * Dd + ag * 4;
        adst[u] = sb + PA_OFF + (uint32_t)(ar * 80 + ag * 16);
        int br = gid >> 5, bg = gid & 31;
        bsrc[u] = Wm + (size_t)br * HC + n0 + bg * 4;
        bdst[u] = sb + PB_OFF + (uint32_t)(br * 544 + bg * 16);
    }

    #pragma unroll
    for (int s = 0; s < 3; s++) {
        #pragma unroll
        for (int u = 0; u < 2; u++) {
            CP_ASYNC16(adst[u] + s * 10240u, asrc[u] + s * 16);
            CP_ASYNC16(bdst[u] + s * 8704u,  bsrc[u] + (size_t)(s * 16) * HC);
        }
        CP_COMMIT();
    }

    for (int kc = 0; kc < 32; ++kc) {
        const int buf = kc & 3;
        CP_WAIT2();
        __syncthreads();
        if (kc < 29) {
            const int s = (kc + 3) & 3, k0 = (kc + 3) * 16;
            #pragma unroll
            for (int u = 0; u < 2; u++) {
                CP_ASYNC16(adst[u] + s * 10240u, asrc[u] + k0);
                CP_ASYNC16(bdst[u] + s * 8704u,  bsrc[u] + (size_t)k0 * HC);
            }
            CP_COMMIT();
        } else {
            CP_COMMIT();
        }

        const uint32_t Ab = sb + PA_OFF + buf * 10240u + (uint32_t)(wm * 64) * 80u;
        const uint32_t Bb = sb + PB_OFF + buf * 8704u + (uint32_t)(wn * 32) * 4u;

        #pragma unroll
        for (int ks = 0; ks < 2; ks++) {
            uint32_t a[4][4];
            #pragma unroll
            for (int mt = 0; mt < 4; mt++) {
                const uint32_t base = Ab + (uint32_t)((mt * 16 + g) * 80 + (ks * 8 + tg) * 4);
                a[mt][0] = tf32u(lds32u(base));
                a[mt][1] = tf32u(lds32u(base + 640u));
                a[mt][2] = tf32u(lds32u(base + 16u));
                a[mt][3] = tf32u(lds32u(base + 656u));
            }
            uint2 bf[4];
            #pragma unroll
            for (int nt = 0; nt < 4; nt++) {
                const uint32_t base = Bb + (uint32_t)((ks * 8 + tg) * 544 + (nt * 8 + g) * 4);
                bf[nt].x = tf32u(lds32u(base));
                bf[nt].y = tf32u(lds32u(base + 2176u));
            }
            #pragma unroll
            for (int mt = 0; mt < 4; mt++)
                #pragma unroll
                for (int nt = 0; nt < 4; nt++)
                    mma8(acc[mt][nt], a[mt][0], a[mt][1], a[mt][2], a[mt][3],
                         bf[nt].x, bf[nt].y);
        }
    }

    // ---- epilogue 1: write g_X (fp32, row-major)
    #pragma unroll
    for (int mt = 0; mt < 4; mt++) {
        const int m = m0 + wm * 64 + mt * 16 + g;
        #pragma unroll
        for (int nt = 0; nt < 4; nt++) {
            const int n = n0 + wn * 32 + nt * 8 + tg * 2;
            *(float2*)(g_X + (size_t)m * HC + n)       = make_float2(acc[mt][nt][0], acc[mt][nt][1]);
            *(float2*)(g_X + (size_t)(m + 8) * HC + n) = make_float2(acc[mt][nt][2], acc[mt][nt][3]);
        }
    }

    // ---- epilogue 2: fused transpose -> g_XTh (fp16, i-pair permuted)
    __syncthreads();   // all MMA/LDS on staging buffers done; reuse SMEM
    // stage tr[hc 128][m 128] halfs, row stride 136 halfs (272B)
    #pragma unroll
    for (int mt = 0; mt < 4; mt++) {
        const int ml = wm * 64 + mt * 16 + g;
        #pragma unroll
        for (int nt = 0; nt < 4; nt++) {
            const int hcl = wn * 32 + nt * 8 + tg * 2;
            sts16(sb + (uint32_t)(hcl * 272 + ml * 2),           f2h(acc[mt][nt][0]));
            sts16(sb + (uint32_t)((hcl + 1) * 272 + ml * 2),     f2h(acc[mt][nt][1]));
            sts16(sb + (uint32_t)(hcl * 272 + (ml + 8) * 2),     f2h(acc[mt][nt][2]));
            sts16(sb + (uint32_t)((hcl + 1) * 272 + (ml + 8) * 2), f2h(acc[mt][nt][3]));
        }
    }
    __syncthreads();

    const int bb = m0 >> 11, mloc = m0 & 2047;
    #pragma unroll 1
    for (int pass = 0; pass < 16; pass++) {
        const int row = pass * 8 + (t >> 5);
        const int ln  = t & 31;
        __half* orow = g_XTh + ((size_t)bb * HC + n0 + row) * Nn + mloc;
        #pragma unroll
        for (int k = 0; k < 2; k++) {
            const int wi = ln + k * 32;
            const int w16 = wi & 15, grp = wi >> 4;
            const int p16 = (w16 & 8) | ((w16 & 3) << 1) | ((w16 >> 2) & 1);
            uint32_t v = lds32u(sb + (uint32_t)(row * 272 + wi * 4));
            *(uint32_t*)(orow + (grp * 16 + p16) * 2) = v;
        }
    }
}

// ---------------------------------------------------------------------------
// Kernel 3: attention scores, warp-per-(b,n) (unchanged R9)
// ---------------------------------------------------------------------------
__global__ __launch_bounds__(256) void att_prep(
    const float* __restrict__ att_src, const float* __restrict__ att_dst)
{
    __shared__ float sa[HC], sdv[HC];
    const int t = threadIdx.x;
    if (t < 128)       ((float4*)sa)[t]        = ((const float4*)att_src)[t];
    else               ((float4*)sdv)[t - 128] = ((const float4*)att_dst)[t - 128];
    __syncthreads();

    const int w = t >> 5, l = t & 31;
    const int bn = blockIdx.x * 8 + w;
    const int b = bn >> 11, n = bn & 2047;
    const float* xp = g_X + (size_t)bn * HC;

    float sp[4], dp[4];
    #pragma unroll
    for (int p = 0; p < 4; p++) {
        const int c = p * 128 + l * 4;
        float4 xv = *(const float4*)(xp + c);
        float4 av = *(const float4*)(sa + c);
        float4 dv = *(const float4*)(sdv + c);
        sp[p] = xv.x * av.x + xv.y * av.y + xv.z * av.z + xv.w * av.w;
        dp[p] = xv.x * dv.x + xv.y * dv.y + xv.z * dv.z + xv.w * dv.w;
    }
    #pragma unroll
    for (int o = 1; o < 16; o <<= 1) {
        #pragma unroll
        for (int p = 0; p < 4; p++) {
            sp[p] += __shfl_xor_sync(0xffffffffu, sp[p], o);
            dp[p] += __shfl_xor_sync(0xffffffffu, dp[p], o);
        }
    }
    const int hi = l >> 4, q = l & 15;
    const int p = q >> 2, v = q & 3;
    const int h = p * 2 + hi;
    const float s = sp[p], d = dp[p];
    const size_t o = ((size_t)b * Hh + h) * Nn + n;
    if      (v == 0) g_EsT [o] = fexp(s - 4.0f);
    else if (v == 1) g_Es2T[o] = fexp(0.2f * s - 4.0f);
    else if (v == 2) g_EdT [o] = fexp(d);
    else             g_Ed2T[o] = fexp(0.2f * d);
}

// ---------------------------------------------------------------------------
// Kernel 4: fused masked-softmax aggregation, fp16 MMA.
// e = max(Es*Ed, Es2*Ed2) [exact leaky-relu identity], mask via AND with
// precomputed adjH half-words (exact). Denominator via ones-column MMA.
// ---------------------------------------------------------------------------
#define XT_OFFB  0u        // 4 stages x 8192B
#define AH_OFFB  32768u    // 4 stages x 8192B (adj mask halfs, swizzled)
#define ES_OFFB  65536u    // 4 x 512B
#define AGG_SMEM 67584u

__global__ void __launch_bounds__(256, 2) gat_agg_mma(
    const float* __restrict__ bias, float* __restrict__ out)
{
    extern __shared__ float sm[];
    const uint32_t sb = smem_u32(sm);

    const int t  = threadIdx.x;
    const int b  = blockIdx.z;
    const int h0 = blockIdx.y * 2;
    const int j0 = blockIdx.x * 128;

    const int wid = t >> 5, lane = t & 31;
    const int chead = wid >> 2, ctw = wid & 3;
    const int g = lane >> 2, tg = lane & 3;

    const size_t bn0 = (size_t)b * Nn;
    const size_t edb = ((size_t)b * Hh + h0 + chead) * Nn + j0;

    // 4 fragment rows this thread owns
    int rows[4]; float ed[4], ed2[4];
    #pragma unroll
    for (int r = 0; r < 4; r++) {
        rows[r] = ctw * 32 + (r >> 1) * 16 + (r & 1) * 8 + g;
        ed[r]  = g_EdT [edb + rows[r]];
        ed2[r] = g_Ed2T[edb + rows[r]];
    }

    float acc[2][8][4];
    #pragma unroll
    for (int m = 0; m < 2; m++)
        #pragma unroll
        for (int n = 0; n < 8; n++)
            #pragma unroll
            for (int r = 0; r < 4; r++) acc[m][n][r] = 0.f;
    float accl[2][4];
    #pragma unroll
    for (int m = 0; m < 2; m++)
        #pragma unroll
        for (int r = 0; r < 4; r++) accl[m][r] = 0.f;

    // cp.async bases: XT and adjH share the thread->granule mapping
    const __half* xsrc[2]; uint32_t xdst[2];
    const unsigned short* asrc[2]; uint32_t adst[2];
    #pragma unroll
    for (int u = 0; u < 2; u++) {
        int gid = u * 256 + t;
        int row = gid >> 2, q = gid & 3;
        int hh = row >> 6, c = row & 63;
        xsrc[u] = g_XTh + ((size_t)b * HC + (size_t)(h0 + hh) * Cc + c) * Nn + q * 8;
        xdst[u] = sb + XT_OFFB + (uint32_t)(row * 64 + ((q ^ ((row >> 1) & 3)) << 4));
        asrc[u] = g_adjH + (bn0 + j0 + row) * Nn + q * 8;
        adst[u] = sb + AH_OFFB + (uint32_t)(row * 64 + ((q ^ ((row >> 1) & 3)) << 4));
    }
    const float* essrc = nullptr; uint32_t esdst = 0;
    if (t < 32) {
        int seg = t >> 3, gi = t & 7;
        int var = seg >> 1, hh = seg & 1;
        const float* tbl = var ? g_Es2T : g_EsT;
        essrc = tbl + ((size_t)b * Hh + h0 + hh) * Nn + gi * 4;
        esdst = sb + ES_OFFB + (uint32_t)(seg * 128 + gi * 16);
    }

    // prologue: stages 0..2
    #pragma unroll
    for (int s = 0; s < 3; s++) {
        #pragma unroll
        for (int u = 0; u < 2; u++) {
            CP_ASYNC16(xdst[u] + s * 8192u, xsrc[u] + s * 32);
            CP_ASYNC16(adst[u] + s * 8192u, asrc[u] + s * 32);
        }
        if (t < 32) CP_ASYNC16(esdst + s * 512u, essrc + s * 32);
        CP_COMMIT();
    }

    for (int ch = 0; ch < 64; ++ch) {
        const int s4 = ch & 3;
        CP_WAIT2();
        __syncthreads();

        if (ch <= 60) {
            const int s = ch + 3, sw = s & 3;
            #pragma unroll
            for (int u = 0; u < 2; u++) {
                CP_ASYNC16(xdst[u] + (uint32_t)sw * 8192u, xsrc[u] + s * 32);
                CP_ASYNC16(adst[u] + (uint32_t)sw * 8192u, asrc[u] + s * 32);
            }
            if (t < 32) CP_ASYNC16(esdst + (uint32_t)sw * 512u, essrc + s * 32);
            CP_COMMIT();
        } else {
            CP_COMMIT();
        }

        const uint32_t esb0 = sb + ES_OFFB + (uint32_t)(s4 * 512 + chead * 128);
        const uint32_t esb2 = esb0 + 256u;
        const uint32_t xtb  = sb + XT_OFFB + (uint32_t)(s4 * 8192 + chead * 4096);
        const uint32_t ahb  = sb + AH_OFFB + (uint32_t)(s4 * 8192);

        #pragma unroll
        for (int ks = 0; ks < 2; ks++) {
            const int sh = ks * 16 + 2 * tg;
            float2 eA  = lds64f(esb0 + (uint32_t)(sh * 4));
            float2 eB  = lds64f(esb0 + (uint32_t)((sh + 8) * 4));
            float2 e2A = lds64f(esb2 + (uint32_t)(sh * 4));
            float2 e2B = lds64f(esb2 + (uint32_t)((sh + 8) * 4));

            uint32_t aT[4], bT[4];
            #pragma unroll
            for (int r = 0; r < 4; r++) {
                const uint32_t rb  = ahb + (uint32_t)(rows[r] * 64);
                const uint32_t sxr = (uint32_t)(((rows[r] >> 1) & 3) << 2);
                uint32_t mA = lds32u(rb + ((((uint32_t)(ks * 8 + tg)) ^ sxr) << 2));
                uint32_t mB = lds32u(rb + ((((uint32_t)(ks * 8 + tg + 4)) ^ sxr) << 2));
                // exp(leaky(x)) == max(exp(x), exp(0.2x)) -- exact identity
                float a0 = fmaxf(eA.x * ed[r], e2A.x * ed2[r]);
                float a1 = fmaxf(eA.y * ed[r], e2A.y * ed2[r]);
                float b0 = fmaxf(eB.x * ed[r], e2B.x * ed2[r]);
                float b1 = fmaxf(eB.y * ed[r], e2B.y * ed2[r]);
                __half2 hA = __floats2half2_rn(a0, a1);
                __half2 hB = __floats2half2_rn(b0, b1);
                aT[r] = (*(uint32_t*)&hA) & mA;   // exact mask (0xFFFF/0)
                bT[r] = (*(uint32_t*)&hB) & mB;
            }

            #pragma unroll
            for (int nt = 0; nt < 8; nt++) {
                const int r = nt * 8 + g;
                const uint32_t g16 = (uint32_t)(ks * 2 + (tg >> 1)) ^ (uint32_t)((r >> 1) & 3);
                uint2 u = lds64u(xtb + (uint32_t)(r * 64) + g16 * 16u + (uint32_t)((tg & 1) * 8));
                mma16(acc[0][nt], aT[0], aT[1], bT[0], bT[1], u.x, u.y);
                mma16(acc[1][nt], aT[2], aT[3], bT[2], bT[3], u.x, u.y);
            }
            mma16(accl[0], aT[0], aT[1], bT[0], bT[1], ONES_H2, ONES_H2);
            mma16(accl[1], aT[2], aT[3], bT[2], bT[3], ONES_H2, ONES_H2);
        }
    }

    // ---- epilogue: normalize, +bias, ELU, store
    const float* bp = bias + (size_t)(h0 + chead) * Cc;
    #pragma unroll
    for (int mt = 0; mt < 2; mt++) {
        const int r0 = ctw * 32 + mt * 16 + g;
        const int r1 = r0 + 8;
        const float inv0 = 1.f / accl[mt][0];
        const float inv1 = 1.f / accl[mt][2];
        float* o0 = out + (bn0 + j0 + r0) * HC + (size_t)(h0 + chead) * Cc;
        float* o1 = out + (bn0 + j0 + r1) * HC + (size_t)(h0 + chead) * Cc;
        #pragma unroll
        for (int nt = 0; nt < 8; nt++) {
            const int c = nt * 8 + tg * 2;
            const float b0v = bp[c], b1v = bp[c + 1];
            float w0 = acc[mt][nt][0] * inv0 + b0v;
            float w1 = acc[mt][nt][1] * inv0 + b1v;
            float w2 = acc[mt][nt][2] * inv1 + b0v;
            float w3 = acc[mt][nt][3] * inv1 + b1v;
            w0 = w0 > 0.f ? w0 : (fexp(w0) - 1.f);
            w1 = w1 > 0.f ? w1 : (fexp(w1) - 1.f);
            w2 = w2 > 0.f ? w2 : (fexp(w2) - 1.f);
            w3 = w3 > 0.f ? w3 : (fexp(w3) - 1.f);
            *(float2*)(o0 + c) = make_float2(w0, w1);
            *(float2*)(o1 + c) = make_float2(w2, w3);
        }
    }
}

// ---------------------------------------------------------------------------
extern "C" void kernel_launch(void* const* d_in, const int* in_sizes, int n_in,
                              void* d_out, int out_size)
{
    const float* feats   = (const float*)d_in[0];
    const int*   adj     = (const int*)  d_in[1];
    const float* W       = (const float*)d_in[2];
    const float* att_src = (const float*)d_in[3];
    const float* att_dst = (const float*)d_in[4];
    const float* bias    = (const float*)d_in[5];
    float*       out     = (float*)d_out;
    (void)in_sizes; (void)n_in; (void)out_size;

    static bool attr_set = false;
    if (!attr_set) {
        cudaFuncSetAttribute(gat_agg_mma,
                             cudaFuncAttributeMaxDynamicSharedMemorySize, AGG_SMEM);
        cudaFuncSetAttribute(gemm_proj_mma,
                             cudaFuncAttributeMaxDynamicSharedMemorySize, PROJ_SMEM);
        attr_set = true;
    }

    pack_adjH<<<dim3(Nn / 32, Nn / 32, Bz), 256>>>(adj);
    gemm_proj_mma<<<dim3((Bz * Nn) / 128, HC / 128), 256, PROJ_SMEM>>>(feats, W);
    att_prep<<<(Bz * Nn) / 8, 256>>>(att_src, att_dst);
    gat_agg_mma<<<dim3(Nn / 128, Hh / 2, Bz), 256, AGG_SMEM>>>(bias, out);
}

// round 11
// speedup vs baseline: 5.0769x; 1.0128x over previous
#include <cuda_runtime.h>
#include <cuda_fp16.h>
#include <cstdint>
#include <math.h>

#define Bz 4
#define Nn 2048
#define Dd 512
#define Hh 8
#define Cc 64
#define HC 512

// ---------------- device scratch ----------------
__device__ float  g_X [(size_t)Bz * Nn * HC];    // projected features [B,N,HC]
__device__ __half g_XTh[(size_t)Bz * HC * Nn];   // transposed fp16, i-pair permuted
__device__ __half g_EsH [(size_t)Bz * Hh * Nn];  // exp(s-4)  fp16 [b][h][n]
__device__ __half g_Es2H[(size_t)Bz * Hh * Nn];  // exp(.2s-4) fp16
__device__ float  g_EdT [(size_t)Bz * Hh * Nn];  // exp(d)   fp32
__device__ float  g_Ed2T[(size_t)Bz * Hh * Nn];  // exp(.2d) fp32
__device__ unsigned short g_adjH[(size_t)Bz * Nn * Nn]; // mask [b][j][i] 0xFFFF/0, diag folded

// ---------------- helpers ----------------
__device__ __forceinline__ uint32_t smem_u32(const void* p) {
    uint32_t a;
    asm("{ .reg .u64 t; cvta.to.shared.u64 t, %1; cvt.u32.u64 %0, t; }"
        : "=r"(a) : "l"(p));
    return a;
}
__device__ __forceinline__ uint32_t tf32u(uint32_t x) {
    uint32_t r;
    asm("cvt.rna.tf32.f32 %0, %1;" : "=r"(r) : "f"(__uint_as_float(x)));
    return r;
}
__device__ __forceinline__ uint2 lds64u(uint32_t a) {
    uint2 v;
    asm volatile("ld.shared.v2.u32 {%0,%1}, [%2];"
                 : "=r"(v.x), "=r"(v.y) : "r"(a));
    return v;
}
__device__ __forceinline__ uint32_t lds32u(uint32_t a) {
    uint32_t v;
    asm volatile("ld.shared.u32 %0, [%1];" : "=r"(v) : "r"(a));
    return v;
}
__device__ __forceinline__ void sts16(uint32_t a, uint16_t v) {
    asm volatile("st.shared.u16 [%0], %1;" :: "r"(a), "h"(v) : "memory");
}
__device__ __forceinline__ uint16_t f2h(float f) {
    __half h = __float2half_rn(f);
    return *(uint16_t*)&h;
}

#define CP_ASYNC16(dst, src) \
    asm volatile("cp.async.cg.shared.global [%0], [%1], 16;" \
                 :: "r"(dst), "l"(src) : "memory")
#define CP_COMMIT()  asm volatile("cp.async.commit_group;" ::: "memory")
#define CP_WAIT2()   asm volatile("cp.async.wait_group 2;" ::: "memory")

// tf32 mma (proj kernel)
__device__ __forceinline__ void mma8(float* d,
                                     uint32_t a0, uint32_t a1, uint32_t a2, uint32_t a3,
                                     uint32_t b0, uint32_t b1) {
    asm volatile(
        "mma.sync.aligned.m16n8k8.row.col.f32.tf32.tf32.f32 "
        "{%0,%1,%2,%3}, {%4,%5,%6,%7}, {%8,%9}, {%0,%1,%2,%3};"
        : "+f"(d[0]), "+f"(d[1]), "+f"(d[2]), "+f"(d[3])
        : "r"(a0), "r"(a1), "r"(a2), "r"(a3), "r"(b0), "r"(b1));
}
// fp16 mma (agg kernel)
__device__ __forceinline__ void mma16(float* d,
                                      uint32_t a0, uint32_t a1, uint32_t a2, uint32_t a3,
                                      uint32_t b0, uint32_t b1) {
    asm volatile(
        "mma.sync.aligned.m16n8k16.row.col.f32.f16.f16.f32 "
        "{%0,%1,%2,%3}, {%4,%5,%6,%7}, {%8,%9}, {%0,%1,%2,%3};"
        : "+f"(d[0]), "+f"(d[1]), "+f"(d[2]), "+f"(d[3])
        : "r"(a0), "r"(a1), "r"(a2), "r"(a3), "r"(b0), "r"(b1));
}
#define ONES_H2 0x3C003C00u

// ---------------- fast exp (FFMA-only) ----------------
__device__ __forceinline__ float fexp(float x) {
    const float LOG2E = 1.4426950408889634f;
    float t = x * LOG2E;
    float z = t + 12582912.0f;
    int   n = __float_as_int(z) - 0x4B400000;
    float r = z - 12582912.0f;
    float f = t - r;
    float u = f * 0.69314718056f;
    float p = 8.3333333e-3f;
    p = p * u + 4.1666667e-2f;
    p = p * u + 1.6666667e-1f;
    p = p * u + 0.5f;
    p = p * u + 1.0f;
    p = p * u + 1.0f;
    return p * __int_as_float((n + 127) << 23);
}

// ---------------------------------------------------------------------------
// Kernel 1: adjacency -> transposed fp16 AND-mask  g_adjH[b][j][i], diag folded
// ---------------------------------------------------------------------------
__global__ __launch_bounds__(256) void pack_adjH(const int* __restrict__ adj)
{
    __shared__ unsigned short ts[32][36];
    const int b  = blockIdx.z;
    const int i0 = blockIdx.y * 32;
    const int j0 = blockIdx.x * 32;
    const int t  = threadIdx.x;
    const int r  = t >> 3;
    const int c4 = t & 7;

    int4 v = *(const int4*)(adj + ((size_t)b * Nn + i0 + r) * Nn + j0 + c4 * 4);
    const int ii = i0 + r;
    ts[r][c4 * 4 + 0] = (v.x != 0 || ii == j0 + c4 * 4 + 0) ? 0xFFFFu : 0u;
    ts[r][c4 * 4 + 1] = (v.y != 0 || ii == j0 + c4 * 4 + 1) ? 0xFFFFu : 0u;
    ts[r][c4 * 4 + 2] = (v.z != 0 || ii == j0 + c4 * 4 + 2) ? 0xFFFFu : 0u;
    ts[r][c4 * 4 + 3] = (v.w != 0 || ii == j0 + c4 * 4 + 3) ? 0xFFFFu : 0u;
    __syncthreads();

    const int jr  = t >> 3;
    const int ic4 = t & 7;
    uint32_t lo = (uint32_t)ts[ic4 * 4 + 0][jr] | ((uint32_t)ts[ic4 * 4 + 1][jr] << 16);
    uint32_t hi = (uint32_t)ts[ic4 * 4 + 2][jr] | ((uint32_t)ts[ic4 * 4 + 3][jr] << 16);
    *(uint2*)(g_adjH + ((size_t)b * Nn + j0 + jr) * Nn + i0 + ic4 * 4) =
        make_uint2(lo, hi);
}

// ---------------------------------------------------------------------------
// Kernel 2: projection GEMM (mma.sync tf32, cp.async 4-stage) + fused
// transposed fp16 epilogue (writes g_X AND g_XTh).
// ---------------------------------------------------------------------------
#define PA_OFF 0u
#define PB_OFF 40960u
#define PROJ_SMEM 75776u

__global__ void __launch_bounds__(256, 2) gemm_proj_mma(
    const float* __restrict__ A, const float* __restrict__ Wm)
{
    extern __shared__ float sm[];
    const uint32_t sb = smem_u32(sm);

    const int t  = threadIdx.x;
    const int m0 = blockIdx.x * 128;
    const int n0 = blockIdx.y * 128;
    const int wid = t >> 5, lane = t & 31;
    const int wm = wid & 1, wn = wid >> 1;
    const int g = lane >> 2, tg = lane & 3;

    float acc[4][4][4];
    #pragma unroll
    for (int i = 0; i < 4; i++)
        #pragma unroll
        for (int j = 0; j < 4; j++)
            #pragma unroll
            for (int r = 0; r < 4; r++) acc[i][j][r] = 0.f;

    const float* asrc[2]; uint32_t adst[2];
    const float* bsrc[2]; uint32_t bdst[2];
    #pragma unroll
    for (int u = 0; u < 2; u++) {
        int gid = u * 256 + t;
        int ar = gid >> 2, ag = gid & 3;
        asrc[u] = A + (size_t)(m0 + ar) * Dd + ag * 4;
        adst[u] = sb + PA_OFF + (uint32_t)(ar * 80 + ag * 16);
        int br = gid >> 5, bg = gid & 31;
        bsrc[u] = Wm + (size_t)br * HC + n0 + bg * 4;
        bdst[u] = sb + PB_OFF + (uint32_t)(br * 544 + bg * 16);
    }

    #pragma unroll
    for (int s = 0; s < 3; s++) {
        #pragma unroll
        for (int u = 0; u < 2; u++) {
            CP_ASYNC16(adst[u] + s * 10240u, asrc[u] + s * 16);
            CP_ASYNC16(bdst[u] + s * 8704u,  bsrc[u] + (size_t)(s * 16) * HC);
        }
        CP_COMMIT();
    }

    for (int kc = 0; kc < 32; ++kc) {
        const int buf = kc & 3;
        CP_WAIT2();
        __syncthreads();
        if (kc < 29) {
            const int s = (kc + 3) & 3, k0 = (kc + 3) * 16;
            #pragma unroll
            for (int u = 0; u < 2; u++) {
                CP_ASYNC16(adst[u] + s * 10240u, asrc[u] + k0);
                CP_ASYNC16(bdst[u] + s * 8704u,  bsrc[u] + (size_t)k0 * HC);
            }
            CP_COMMIT();
        } else {
            CP_COMMIT();
        }

        const uint32_t Ab = sb + PA_OFF + buf * 10240u + (uint32_t)(wm * 64) * 80u;
        const uint32_t Bb = sb + PB_OFF + buf * 8704u + (uint32_t)(wn * 32) * 4u;

        #pragma unroll
        for (int ks = 0; ks < 2; ks++) {
            uint32_t a[4][4];
            #pragma unroll
            for (int mt = 0; mt < 4; mt++) {
                const uint32_t base = Ab + (uint32_t)((mt * 16 + g) * 80 + (ks * 8 + tg) * 4);
                a[mt][0] = tf32u(lds32u(base));
                a[mt][1] = tf32u(lds32u(base + 640u));
                a[mt][2] = tf32u(lds32u(base + 16u));
                a[mt][3] = tf32u(lds32u(base + 656u));
            }
            uint2 bf[4];
            #pragma unroll
            for (int nt = 0; nt < 4; nt++) {
                const uint32_t base = Bb + (uint32_t)((ks * 8 + tg) * 544 + (nt * 8 + g) * 4);
                bf[nt].x = tf32u(lds32u(base));
                bf[nt].y = tf32u(lds32u(base + 2176u));
            }
            #pragma unroll
            for (int mt = 0; mt < 4; mt++)
                #pragma unroll
                for (int nt = 0; nt < 4; nt++)
                    mma8(acc[mt][nt], a[mt][0], a[mt][1], a[mt][2], a[mt][3],
                         bf[nt].x, bf[nt].y);
        }
    }

    // epilogue 1: g_X (fp32 row-major)
    #pragma unroll
    for (int mt = 0; mt < 4; mt++) {
        const int m = m0 + wm * 64 + mt * 16 + g;
        #pragma unroll
        for (int nt = 0; nt < 4; nt++) {
            const int n = n0 + wn * 32 + nt * 8 + tg * 2;
            *(float2*)(g_X + (size_t)m * HC + n)       = make_float2(acc[mt][nt][0], acc[mt][nt][1]);
            *(float2*)(g_X + (size_t)(m + 8) * HC + n) = make_float2(acc[mt][nt][2], acc[mt][nt][3]);
        }
    }

    // epilogue 2: fused transpose -> g_XTh (fp16, i-pair permuted)
    __syncthreads();
    #pragma unroll
    for (int mt = 0; mt < 4; mt++) {
        const int ml = wm * 64 + mt * 16 + g;
        #pragma unroll
        for (int nt = 0; nt < 4; nt++) {
            const int hcl = wn * 32 + nt * 8 + tg * 2;
            sts16(sb + (uint32_t)(hcl * 272 + ml * 2),             f2h(acc[mt][nt][0]));
            sts16(sb + (uint32_t)((hcl + 1) * 272 + ml * 2),       f2h(acc[mt][nt][1]));
            sts16(sb + (uint32_t)(hcl * 272 + (ml + 8) * 2),       f2h(acc[mt][nt][2]));
            sts16(sb + (uint32_t)((hcl + 1) * 272 + (ml + 8) * 2), f2h(acc[mt][nt][3]));
        }
    }
    __syncthreads();

    const int bb = m0 >> 11, mloc = m0 & 2047;
    #pragma unroll 1
    for (int pass = 0; pass < 16; pass++) {
        const int row = pass * 8 + (t >> 5);
        const int ln  = t & 31;
        __half* orow = g_XTh + ((size_t)bb * HC + n0 + row) * Nn + mloc;
        #pragma unroll
        for (int k = 0; k < 2; k++) {
            const int wi = ln + k * 32;
            const int w16 = wi & 15, grp = wi >> 4;
            const int p16 = (w16 & 8) | ((w16 & 3) << 1) | ((w16 >> 2) & 1);
            uint32_t v = lds32u(sb + (uint32_t)(row * 272 + wi * 4));
            *(uint32_t*)(orow + (grp * 16 + p16) * 2) = v;
        }
    }
}

// ---------------------------------------------------------------------------
// Kernel 3: attention scores, warp-per-(b,n). Es tables now fp16.
// ---------------------------------------------------------------------------
__global__ __launch_bounds__(256) void att_prep(
    const float* __restrict__ att_src, const float* __restrict__ att_dst)
{
    __shared__ float sa[HC], sdv[HC];
    const int t = threadIdx.x;
    if (t < 128)       ((float4*)sa)[t]        = ((const float4*)att_src)[t];
    else               ((float4*)sdv)[t - 128] = ((const float4*)att_dst)[t - 128];
    __syncthreads();

    const int w = t >> 5, l = t & 31;
    const int bn = blockIdx.x * 8 + w;
    const int b = bn >> 11, n = bn & 2047;
    const float* xp = g_X + (size_t)bn * HC;

    float sp[4], dp[4];
    #pragma unroll
    for (int p = 0; p < 4; p++) {
        const int c = p * 128 + l * 4;
        float4 xv = *(const float4*)(xp + c);
        float4 av = *(const float4*)(sa + c);
        float4 dv = *(const float4*)(sdv + c);
        sp[p] = xv.x * av.x + xv.y * av.y + xv.z * av.z + xv.w * av.w;
        dp[p] = xv.x * dv.x + xv.y * dv.y + xv.z * dv.z + xv.w * dv.w;
    }
    #pragma unroll
    for (int o = 1; o < 16; o <<= 1) {
        #pragma unroll
        for (int p = 0; p < 4; p++) {
            sp[p] += __shfl_xor_sync(0xffffffffu, sp[p], o);
            dp[p] += __shfl_xor_sync(0xffffffffu, dp[p], o);
        }
    }
    const int hi = l >> 4, q = l & 15;
    const int p = q >> 2, v = q & 3;
    const int h = p * 2 + hi;
    const float s = sp[p], d = dp[p];
    const size_t o = ((size_t)b * Hh + h) * Nn + n;
    if      (v == 0) g_EsH [o] = __float2half_rn(fexp(s - 4.0f));
    else if (v == 1) g_Es2H[o] = __float2half_rn(fexp(0.2f * s - 4.0f));
    else if (v == 2) g_EdT [o] = fexp(d);
    else             g_Ed2T[o] = fexp(0.2f * d);
}

// ---------------------------------------------------------------------------
// Kernel 4: fused masked-softmax aggregation, fp16 MMA + half2 e-production:
// e = HMAX2(HMUL2(Es, ed), HMUL2(Es2, ed2)) & mask   (packed, no CVT)
// ---------------------------------------------------------------------------
#define XT_OFFB  0u        // 4 stages x 8192B
#define AH_OFFB  32768u    // 4 stages x 8192B
#define ES_OFFB  65536u    // 4 stages x 256B ([var2][head2][32 halfs])
#define AGG_SMEM 66560u

__global__ void __launch_bounds__(256, 2) gat_agg_mma(
    const float* __restrict__ bias, float* __restrict__ out)
{
    extern __shared__ float sm[];
    const uint32_t sb = smem_u32(sm);

    const int t  = threadIdx.x;
    const int b  = blockIdx.z;
    const int h0 = blockIdx.y * 2;
    const int j0 = blockIdx.x * 128;

    const int wid = t >> 5, lane = t & 31;
    const int chead = wid >> 2, ctw = wid & 3;
    const int g = lane >> 2, tg = lane & 3;

    const size_t bn0 = (size_t)b * Nn;
    const size_t edb = ((size_t)b * Hh + h0 + chead) * Nn + j0;

    // 4 fragment rows this thread owns; ed/ed2 as broadcast half2
    int rows[4]; __half2 edh[4], ed2h[4];
    #pragma unroll
    for (int r = 0; r < 4; r++) {
        rows[r] = ctw * 32 + (r >> 1) * 16 + (r & 1) * 8 + g;
        edh[r]  = __half2half2(__float2half_rn(g_EdT [edb + rows[r]]));
        ed2h[r] = __half2half2(__float2half_rn(g_Ed2T[edb + rows[r]]));
    }

    float acc[2][8][4];
    #pragma unroll
    for (int m = 0; m < 2; m++)
        #pragma unroll
        for (int n = 0; n < 8; n++)
            #pragma unroll
            for (int r = 0; r < 4; r++) acc[m][n][r] = 0.f;
    float accl[2][4];
    #pragma unroll
    for (int m = 0; m < 2; m++)
        #pragma unroll
        for (int r = 0; r < 4; r++) accl[m][r] = 0.f;

    // cp.async bases
    const __half* xsrc[2]; uint32_t xdst[2];
    const unsigned short* asrc[2]; uint32_t adst[2];
    #pragma unroll
    for (int u = 0; u < 2; u++) {
        int gid = u * 256 + t;
        int row = gid >> 2, q = gid & 3;
        int hh = row >> 6, c = row & 63;
        xsrc[u] = g_XTh + ((size_t)b * HC + (size_t)(h0 + hh) * Cc + c) * Nn + q * 8;
        xdst[u] = sb + XT_OFFB + (uint32_t)(row * 64 + ((q ^ ((row >> 1) & 3)) << 4));
        asrc[u] = g_adjH + (bn0 + j0 + row) * Nn + q * 8;
        adst[u] = sb + AH_OFFB + (uint32_t)(row * 64 + ((q ^ ((row >> 1) & 3)) << 4));
    }
    const __half* essrc = nullptr; uint32_t esdst = 0;
    if (t < 16) {
        int seg = t >> 2, gi = t & 3;             // seg = var*2 + head
        int var = seg >> 1, hh = seg & 1;
        const __half* tbl = var ? g_Es2H : g_EsH;
        essrc = tbl + ((size_t)b * Hh + h0 + hh) * Nn + gi * 8;
        esdst = sb + ES_OFFB + (uint32_t)(seg * 64 + gi * 16);
    }

    // prologue: stages 0..2
    #pragma unroll
    for (int s = 0; s < 3; s++) {
        #pragma unroll
        for (int u = 0; u < 2; u++) {
            CP_ASYNC16(xdst[u] + s * 8192u, xsrc[u] + s * 32);
            CP_ASYNC16(adst[u] + s * 8192u, asrc[u] + s * 32);
        }
        if (t < 16) CP_ASYNC16(esdst + s * 256u, essrc + s * 32);
        CP_COMMIT();
    }

    for (int ch = 0; ch < 64; ++ch) {
        const int s4 = ch & 3;
        CP_WAIT2();
        __syncthreads();

        if (ch <= 60) {
            const int s = ch + 3, sw = s & 3;
            #pragma unroll
            for (int u = 0; u < 2; u++) {
                CP_ASYNC16(xdst[u] + (uint32_t)sw * 8192u, xsrc[u] + s * 32);
                CP_ASYNC16(adst[u] + (uint32_t)sw * 8192u, asrc[u] + s * 32);
            }
            if (t < 16) CP_ASYNC16(esdst + (uint32_t)sw * 256u, essrc + s * 32);
            CP_COMMIT();
        } else {
            CP_COMMIT();
        }

        const uint32_t esb0 = sb + ES_OFFB + (uint32_t)(s4 * 256 + chead * 64);
        const uint32_t esb2 = esb0 + 128u;
        const uint32_t xtb  = sb + XT_OFFB + (uint32_t)(s4 * 8192 + chead * 4096);
        const uint32_t ahb  = sb + AH_OFFB + (uint32_t)(s4 * 8192);

        #pragma unroll
        for (int ks = 0; ks < 2; ks++) {
            const uint32_t eo = (uint32_t)(ks * 32 + tg * 4);
            uint32_t uesA = lds32u(esb0 + eo);
            uint32_t uesB = lds32u(esb0 + eo + 16u);
            uint32_t ue2A = lds32u(esb2 + eo);
            uint32_t ue2B = lds32u(esb2 + eo + 16u);
            const __half2 esA = *(__half2*)&uesA, esB = *(__half2*)&uesB;
            const __half2 e2A = *(__half2*)&ue2A, e2B = *(__half2*)&ue2B;

            uint32_t aT[4], bT[4];
            #pragma unroll
            for (int r = 0; r < 4; r++) {
                const uint32_t rb  = ahb + (uint32_t)(rows[r] * 64);
                const uint32_t sxr = (uint32_t)(((rows[r] >> 1) & 3) << 2);
                uint32_t mA = lds32u(rb + ((((uint32_t)(ks * 8 + tg)) ^ sxr) << 2));
                uint32_t mB = lds32u(rb + ((((uint32_t)(ks * 8 + tg + 4)) ^ sxr) << 2));
                __half2 va = __hmax2(__hmul2(esA, edh[r]), __hmul2(e2A, ed2h[r]));
                __half2 vb = __hmax2(__hmul2(esB, edh[r]), __hmul2(e2B, ed2h[r]));
                aT[r] = (*(uint32_t*)&va) & mA;
                bT[r] = (*(uint32_t*)&vb) & mB;
            }

            #pragma unroll
            for (int nt = 0; nt < 8; nt++) {
                const int r = nt * 8 + g;
                const uint32_t g16 = (uint32_t)(ks * 2 + (tg >> 1)) ^ (uint32_t)((r >> 1) & 3);
                uint2 u = lds64u(xtb + (uint32_t)(r * 64) + g16 * 16u + (uint32_t)((tg & 1) * 8));
                mma16(acc[0][nt], aT[0], aT[1], bT[0], bT[1], u.x, u.y);
                mma16(acc[1][nt], aT[2], aT[3], bT[2], bT[3], u.x, u.y);
            }
            mma16(accl[0], aT[0], aT[1], bT[0], bT[1], ONES_H2, ONES_H2);
            mma16(accl[1], aT[2], aT[3], bT[2], bT[3], ONES_H2, ONES_H2);
        }
    }

    // ---- epilogue: normalize, +bias, ELU, store
    const float* bp = bias + (size_t)(h0 + chead) * Cc;
    #pragma unroll
    for (int mt = 0; mt < 2; mt++) {
        const int r0 = ctw * 32 + mt * 16 + g;
        const int r1 = r0 + 8;
        const float inv0 = 1.f / accl[mt][0];
        const float inv1 = 1.f / accl[mt][2];
        float* o0 = out + (bn0 + j0 + r0) * HC + (size_t)(h0 + chead) * Cc;
        float* o1 = out + (bn0 + j0 + r1) * HC + (size_t)(h0 + chead) * Cc;
        #pragma unroll
        for (int nt = 0; nt < 8; nt++) {
            const int c = nt * 8 + tg * 2;
            const float b0v = bp[c], b1v = bp[c + 1];
            float w0 = acc[mt][nt][0] * inv0 + b0v;
            float w1 = acc[mt][nt][1] * inv0 + b1v;
            float w2 = acc[mt][nt][2] * inv1 + b0v;
            float w3 = acc[mt][nt][3] * inv1 + b1v;
            w0 = w0 > 0.f ? w0 : (fexp(w0) - 1.f);
            w1 = w1 > 0.f ? w1 : (fexp(w1) - 1.f);
            w2 = w2 > 0.f ? w2 : (fexp(w2) - 1.f);
            w3 = w3 > 0.f ? w3 : (fexp(w3) - 1.f);
            *(float2*)(o0 + c) = make_float2(w0, w1);
            *(float2*)(o1 + c) = make_float2(w2, w3);
        }
    }
}

// ---------------------------------------------------------------------------
extern "C" void kernel_launch(void* const* d_in, const int* in_sizes, int n_in,
                              void* d_out, int out_size)
{
    const float* feats   = (const float*)d_in[0];
    const int*   adj     = (const int*)  d_in[1];
    const float* W       = (const float*)d_in[2];
    const float* att_src = (const float*)d_in[3];
    const float* att_dst = (const float*)d_in[4];
    const float* bias    = (const float*)d_in[5];
    float*       out     = (float*)d_out;
    (void)in_sizes; (void)n_in; (void)out_size;

    static bool attr_set = false;
    if (!attr_set) {
        cudaFuncSetAttribute(gat_agg_mma,
                             cudaFuncAttributeMaxDynamicSharedMemorySize, AGG_SMEM);
        cudaFuncSetAttribute(gemm_proj_mma,
                             cudaFuncAttributeMaxDynamicSharedMemorySize, PROJ_SMEM);
        attr_set = true;
    }

    pack_adjH<<<dim3(Nn / 32, Nn / 32, Bz), 256>>>(adj);
    gemm_proj_mma<<<dim3((Bz * Nn) / 128, HC / 128), 256, PROJ_SMEM>>>(feats, W);
    att_prep<<<(Bz * Nn) / 8, 256>>>(att_src, att_dst);
    gat_agg_mma<<<dim3(Nn / 128, Hh / 2, Bz), 256, AGG_SMEM>>>(bias, out);
}